// round 3
// baseline (speedup 1.0000x reference)
#include <cuda_runtime.h>
#include <math.h>

#define BATCH 2
#define SEQ 2048
#define EMB 1024
#define NH 16
#define HD 64
#define MROWS (BATCH * SEQ)   // 4096

// ---------------- device scratch (no allocations allowed) ----------------
__device__ float g_Q[(size_t)MROWS * EMB];
__device__ float g_K[(size_t)MROWS * EMB];
__device__ float g_V[(size_t)MROWS * EMB];
__device__ float g_ATT[(size_t)MROWS * EMB];
__device__ float g_TMP[(size_t)MROWS * EMB];

// ---------------- SGEMM: C = A[M,K] @ B[K,N] + bias (+ residual) ----------------
#define BM 128
#define BN 128
#define BK 16
#define TM 8
#define TN 8

template <bool ADD_RES>
__global__ __launch_bounds__(256)
void sgemm_bias(const float* __restrict__ A, const float* __restrict__ B,
                const float* __restrict__ bias, const float* __restrict__ res,
                float* __restrict__ C, int M, int N, int K)
{
    __shared__ float As[BK][BM + 4];   // transposed: As[k][m]
    __shared__ float Bs[BK][BN + 4];   // Bs[k][n]

    const int t = threadIdx.x;
    const int m0g = blockIdx.y * BM;
    const int n0g = blockIdx.x * BN;
    const int ty = t >> 4;
    const int tx = t & 15;
    const int mr = ty * TM;
    const int nr = tx * TN;

    float acc[TM][TN];
#pragma unroll
    for (int i = 0; i < TM; i++)
#pragma unroll
        for (int j = 0; j < TN; j++) acc[i][j] = 0.f;

    for (int k0 = 0; k0 < K; k0 += BK) {
        // A tile: 128 rows x 16 cols -> 512 float4, 2 per thread, store transposed
#pragma unroll
        for (int u = 0; u < 2; u++) {
            int lin = t + u * 256;
            int m = lin >> 2;
            int k4 = (lin & 3) * 4;
            float4 v = *(const float4*)&A[(size_t)(m0g + m) * K + k0 + k4];
            As[k4 + 0][m] = v.x;
            As[k4 + 1][m] = v.y;
            As[k4 + 2][m] = v.z;
            As[k4 + 3][m] = v.w;
        }
        // B tile: 16 rows x 128 cols -> 512 float4, 2 per thread, direct
#pragma unroll
        for (int u = 0; u < 2; u++) {
            int lin = t + u * 256;
            int k = lin >> 5;
            int n4 = (lin & 31) * 4;
            *(float4*)&Bs[k][n4] = *(const float4*)&B[(size_t)(k0 + k) * N + n0g + n4];
        }
        __syncthreads();

#pragma unroll
        for (int k = 0; k < BK; k++) {
            float a[TM], b[TN];
            *(float4*)&a[0] = *(float4*)&As[k][mr];
            *(float4*)&a[4] = *(float4*)&As[k][mr + 4];
            *(float4*)&b[0] = *(float4*)&Bs[k][nr];
            *(float4*)&b[4] = *(float4*)&Bs[k][nr + 4];
#pragma unroll
            for (int i = 0; i < TM; i++)
#pragma unroll
                for (int j = 0; j < TN; j++) acc[i][j] += a[i] * b[j];
        }
        __syncthreads();
    }

    // epilogue
#pragma unroll
    for (int i = 0; i < TM; i++) {
        int row = m0g + mr + i;
#pragma unroll
        for (int j4 = 0; j4 < TN; j4 += 4) {
            int col = n0g + nr + j4;
            float4 o;
            o.x = acc[i][j4 + 0] + bias[col + 0];
            o.y = acc[i][j4 + 1] + bias[col + 1];
            o.z = acc[i][j4 + 2] + bias[col + 2];
            o.w = acc[i][j4 + 3] + bias[col + 3];
            if (ADD_RES) {
                float4 r = *(const float4*)&res[(size_t)row * N + col];
                o.x += r.x; o.y += r.y; o.z += r.z; o.w += r.w;
            }
            *(float4*)&C[(size_t)row * N + col] = o;
        }
    }
}

// ---------------- attention: flash-style, one CTA per (b, h, 64-q tile) ----------------
#define ASTR 68   // padded smem row stride (floats), 16B aligned

__global__ __launch_bounds__(256)
void attn_kernel(const float* __restrict__ Q, const float* __restrict__ K,
                 const float* __restrict__ V, float* __restrict__ O)
{
    extern __shared__ float sm[];
    float* Qs = sm;                 // [64][ASTR], transposed: Qs[d][q]
    float* Ks = sm + 64 * ASTR;     // [64][ASTR], transposed: Ks[d][j]; later aliased as Ps[j][q]
    float* Vs = sm + 2 * 64 * ASTR; // [64][ASTR], direct: Vs[j][d]

    const int t = threadIdx.x;
    const int ty = t >> 4;          // 0..15 -> q rows ty*4..+3
    const int tx = t & 15;          // 0..15 -> cols tx*4..+3
    const int q0 = blockIdx.x * 64;
    const int h = blockIdx.y;
    const int b = blockIdx.z;

    const float* Qb = Q + (size_t)b * SEQ * EMB + h * HD;
    const float* Kb = K + (size_t)b * SEQ * EMB + h * HD;
    const float* Vb = V + (size_t)b * SEQ * EMB + h * HD;

    // load Q tile transposed (64 rows x 64 dims)
#pragma unroll
    for (int u = 0; u < 4; u++) {
        int lin = t + u * 256;
        int r = lin >> 4;
        int c4 = (lin & 15) * 4;
        float4 v = *(const float4*)&Qb[(size_t)(q0 + r) * EMB + c4];
        Qs[(c4 + 0) * ASTR + r] = v.x;
        Qs[(c4 + 1) * ASTR + r] = v.y;
        Qs[(c4 + 2) * ASTR + r] = v.z;
        Qs[(c4 + 3) * ASTR + r] = v.w;
    }

    float m_[4], l_[4], o_[4][4];
#pragma unroll
    for (int i = 0; i < 4; i++) {
        m_[i] = -1e30f;
        l_[i] = 0.f;
#pragma unroll
        for (int j = 0; j < 4; j++) o_[i][j] = 0.f;
    }

    for (int kv0 = 0; kv0 < SEQ; kv0 += 64) {
        __syncthreads();  // previous P@V done before overwriting Ks/Vs (also covers Q load, iter 0)
        // load K transposed, V direct
#pragma unroll
        for (int u = 0; u < 4; u++) {
            int lin = t + u * 256;
            int r = lin >> 4;
            int c4 = (lin & 15) * 4;
            float4 kv = *(const float4*)&Kb[(size_t)(kv0 + r) * EMB + c4];
            Ks[(c4 + 0) * ASTR + r] = kv.x;
            Ks[(c4 + 1) * ASTR + r] = kv.y;
            Ks[(c4 + 2) * ASTR + r] = kv.z;
            Ks[(c4 + 3) * ASTR + r] = kv.w;
            float4 vv = *(const float4*)&Vb[(size_t)(kv0 + r) * EMB + c4];
            *(float4*)&Vs[r * ASTR + c4] = vv;
        }
        __syncthreads();

        // S = (Q @ K^T) * 1/sqrt(64)
        float s[4][4];
#pragma unroll
        for (int i = 0; i < 4; i++)
#pragma unroll
            for (int j = 0; j < 4; j++) s[i][j] = 0.f;

#pragma unroll 16
        for (int d = 0; d < 64; d++) {
            float4 a = *(float4*)&Qs[d * ASTR + ty * 4];
            float4 bb = *(float4*)&Ks[d * ASTR + tx * 4];
            float av[4] = {a.x, a.y, a.z, a.w};
            float bv[4] = {bb.x, bb.y, bb.z, bb.w};
#pragma unroll
            for (int i = 0; i < 4; i++)
#pragma unroll
                for (int j = 0; j < 4; j++) s[i][j] += av[i] * bv[j];
        }

        float p[4][4], alpha[4];
#pragma unroll
        for (int i = 0; i < 4; i++) {
            float rm = s[i][0];
#pragma unroll
            for (int j = 1; j < 4; j++) rm = fmaxf(rm, s[i][j]);
            rm *= 0.125f;
#pragma unroll
            for (int off = 1; off < 16; off <<= 1)
                rm = fmaxf(rm, __shfl_xor_sync(0xffffffffu, rm, off));
            float mnew = fmaxf(m_[i], rm);
            alpha[i] = __expf(m_[i] - mnew);
            float rs = 0.f;
#pragma unroll
            for (int j = 0; j < 4; j++) {
                p[i][j] = __expf(s[i][j] * 0.125f - mnew);
                rs += p[i][j];
            }
#pragma unroll
            for (int off = 1; off < 16; off <<= 1)
                rs += __shfl_xor_sync(0xffffffffu, rs, off);
            l_[i] = l_[i] * alpha[i] + rs;
            m_[i] = mnew;
#pragma unroll
            for (int j = 0; j < 4; j++) o_[i][j] *= alpha[i];
        }

        __syncthreads();  // everyone done reading Ks before it becomes Ps
        // store P transposed into Ks region: Ps[kv][q]
#pragma unroll
        for (int i = 0; i < 4; i++)
#pragma unroll
            for (int j = 0; j < 4; j++)
                Ks[(tx * 4 + j) * ASTR + (ty * 4 + i)] = p[i][j];
        __syncthreads();

        // O += P @ V   (inner dim = kv)
#pragma unroll 16
        for (int j = 0; j < 64; j++) {
            float4 a = *(float4*)&Ks[j * ASTR + ty * 4];   // P[j][q rows]
            float4 bv = *(float4*)&Vs[j * ASTR + tx * 4];  // V[j][d cols]
            float av[4] = {a.x, a.y, a.z, a.w};
            float vv[4] = {bv.x, bv.y, bv.z, bv.w};
#pragma unroll
            for (int i = 0; i < 4; i++)
#pragma unroll
                for (int j2 = 0; j2 < 4; j2++) o_[i][j2] += av[i] * vv[j2];
        }
    }

    // finalize: divide by l, write [b, q, h*64 + d]
#pragma unroll
    for (int i = 0; i < 4; i++) {
        float inv = 1.f / l_[i];
        int row = b * SEQ + q0 + ty * 4 + i;
        float4 o;
        o.x = o_[i][0] * inv;
        o.y = o_[i][1] * inv;
        o.z = o_[i][2] * inv;
        o.w = o_[i][3] * inv;
        *(float4*)&O[(size_t)row * EMB + h * HD + tx * 4] = o;
    }
}

// ---------------- LayerNorm (per row of 1024) ----------------
__global__ __launch_bounds__(256)
void layernorm_kernel(const float* __restrict__ X, const float* __restrict__ gamma,
                      const float* __restrict__ beta, float* __restrict__ out)
{
    __shared__ float ssum[256];
    __shared__ float ssq[256];
    const int row = blockIdx.x;
    const int t = threadIdx.x;
    const float* x = X + (size_t)row * EMB;

    float4 v = *(const float4*)&x[t * 4];
    float s = v.x + v.y + v.z + v.w;
    float sq = v.x * v.x + v.y * v.y + v.z * v.z + v.w * v.w;
    ssum[t] = s;
    ssq[t] = sq;
    __syncthreads();
#pragma unroll
    for (int off = 128; off > 0; off >>= 1) {
        if (t < off) {
            ssum[t] += ssum[t + off];
            ssq[t] += ssq[t + off];
        }
        __syncthreads();
    }
    const float mu = ssum[0] * (1.f / EMB);
    const float var = ssq[0] * (1.f / EMB) - mu * mu;
    const float rs = rsqrtf(var + 1e-5f);

    float4 g = *(const float4*)&gamma[t * 4];
    float4 be = *(const float4*)&beta[t * 4];
    float4 o;
    o.x = (v.x - mu) * rs * g.x + be.x;
    o.y = (v.y - mu) * rs * g.y + be.y;
    o.z = (v.z - mu) * rs * g.z + be.z;
    o.w = (v.w - mu) * rs * g.w + be.w;
    *(float4*)&out[(size_t)row * EMB + t * 4] = o;
}

// ---------------- launch ----------------
extern "C" void kernel_launch(void* const* d_in, const int* in_sizes, int n_in,
                              void* d_out, int out_size)
{
    const float* query = (const float*)d_in[0];
    const float* key   = (const float*)d_in[1];
    const float* value = (const float*)d_in[2];
    const float* Wq    = (const float*)d_in[3];
    const float* bq    = (const float*)d_in[4];
    const float* Wk    = (const float*)d_in[5];
    const float* bk    = (const float*)d_in[6];
    const float* Wv    = (const float*)d_in[7];
    const float* bv    = (const float*)d_in[8];
    const float* Wo    = (const float*)d_in[9];
    const float* bo    = (const float*)d_in[10];
    const float* ln_g  = (const float*)d_in[11];
    const float* ln_b  = (const float*)d_in[12];
    float* out = (float*)d_out;

    float *Qp, *Kp, *Vp, *ATTp, *TMPp;
    cudaGetSymbolAddress((void**)&Qp, g_Q);
    cudaGetSymbolAddress((void**)&Kp, g_K);
    cudaGetSymbolAddress((void**)&Vp, g_V);
    cudaGetSymbolAddress((void**)&ATTp, g_ATT);
    cudaGetSymbolAddress((void**)&TMPp, g_TMP);

    const int smem_attn = 3 * 64 * ASTR * sizeof(float);  // 52224 B
    static bool attr_set = false;
    if (!attr_set) {
        cudaFuncSetAttribute(attn_kernel, cudaFuncAttributeMaxDynamicSharedMemorySize, smem_attn);
        attr_set = true;
    }

    dim3 gemm_grid(EMB / BN, MROWS / BM);  // (8, 32)

    // projections
    sgemm_bias<false><<<gemm_grid, 256>>>(query, Wq, bq, nullptr, Qp, MROWS, EMB, EMB);
    sgemm_bias<false><<<gemm_grid, 256>>>(key,   Wk, bk, nullptr, Kp, MROWS, EMB, EMB);
    sgemm_bias<false><<<gemm_grid, 256>>>(value, Wv, bv, nullptr, Vp, MROWS, EMB, EMB);

    // attention
    dim3 attn_grid(SEQ / 64, NH, BATCH);   // (32, 16, 2)
    attn_kernel<<<attn_grid, 256, smem_attn>>>(Qp, Kp, Vp, ATTp);

    // output projection + residual
    sgemm_bias<true><<<gemm_grid, 256>>>(ATTp, Wo, bo, query, TMPp, MROWS, EMB, EMB);

    // layernorm
    layernorm_kernel<<<MROWS, 256>>>(TMPp, ln_g, ln_b, out);
}

// round 5
// speedup vs baseline: 1.1649x; 1.1649x over previous
#include <cuda_runtime.h>
#include <cuda_bf16.h>
#include <math.h>
#include <stdint.h>

#define BATCH 2
#define SEQ 2048
#define EMB 1024
#define NH 16
#define HD 64
#define MROWS (BATCH * SEQ)   // 4096
#define NELEM ((size_t)MROWS * EMB)

// ---------------- device scratch (no allocations allowed) ----------------
__device__ float g_Q[NELEM];
__device__ float g_K[NELEM];
__device__ float g_V[NELEM];
__device__ float g_ATT[NELEM];
__device__ float g_TMP[NELEM];

__device__ __nv_bfloat16 g_qh[NELEM], g_ql[NELEM];
__device__ __nv_bfloat16 g_kh[NELEM], g_kl[NELEM];
__device__ __nv_bfloat16 g_vh[NELEM], g_vl[NELEM];
__device__ __nv_bfloat16 g_oh[NELEM], g_ol[NELEM];
__device__ __nv_bfloat16 g_wqh[EMB*EMB], g_wql[EMB*EMB];
__device__ __nv_bfloat16 g_wkh[EMB*EMB], g_wkl[EMB*EMB];
__device__ __nv_bfloat16 g_wvh[EMB*EMB], g_wvl[EMB*EMB];
__device__ __nv_bfloat16 g_woh[EMB*EMB], g_wol[EMB*EMB];

// ---------------- fp32 -> bf16 hi/lo split ----------------
__global__ __launch_bounds__(256)
void fsplit(const float* __restrict__ x, __nv_bfloat16* __restrict__ hi,
            __nv_bfloat16* __restrict__ lo)
{
    size_t i = ((size_t)blockIdx.x * 256 + threadIdx.x) * 4;
    float4 v = *(const float4*)(x + i);
    float vv[4] = {v.x, v.y, v.z, v.w};
    uint32_t ph[2], pl[2];
#pragma unroll
    for (int p = 0; p < 2; p++) {
        __nv_bfloat16 h0 = __float2bfloat16(vv[2*p]);
        __nv_bfloat16 h1 = __float2bfloat16(vv[2*p+1]);
        __nv_bfloat16 l0 = __float2bfloat16(vv[2*p]   - __bfloat162float(h0));
        __nv_bfloat16 l1 = __float2bfloat16(vv[2*p+1] - __bfloat162float(h1));
        ph[p] = (uint32_t)__bfloat16_as_ushort(h0) | ((uint32_t)__bfloat16_as_ushort(h1) << 16);
        pl[p] = (uint32_t)__bfloat16_as_ushort(l0) | ((uint32_t)__bfloat16_as_ushort(l1) << 16);
    }
    *(uint2*)(hi + i) = make_uint2(ph[0], ph[1]);
    *(uint2*)(lo + i) = make_uint2(pl[0], pl[1]);
}

// ---------------- W[K,N] -> Wt[N,K] transpose + hi/lo split ----------------
__global__ __launch_bounds__(256)
void wsplitT(const float* __restrict__ W, __nv_bfloat16* __restrict__ th,
             __nv_bfloat16* __restrict__ tl)
{
    __shared__ float tile[32][33];
    const int n0 = blockIdx.x * 32, k0 = blockIdx.y * 32;
    const int tx = threadIdx.x, ty0 = threadIdx.y;  // (32, 8)
#pragma unroll
    for (int i = 0; i < 4; i++) {
        int ty = ty0 + i * 8;
        tile[ty][tx] = W[(size_t)(k0 + ty) * EMB + n0 + tx];
    }
    __syncthreads();
#pragma unroll
    for (int i = 0; i < 4; i++) {
        int ty = ty0 + i * 8;
        float x = tile[tx][ty];  // W[k0+tx][n0+ty]
        __nv_bfloat16 h = __float2bfloat16(x);
        __nv_bfloat16 l = __float2bfloat16(x - __bfloat162float(h));
        th[(size_t)(n0 + ty) * EMB + k0 + tx] = h;
        tl[(size_t)(n0 + ty) * EMB + k0 + tx] = l;
    }
}

// ---------------- mma.sync bf16 split GEMM: C = A @ Bt^T + bias (+res) ----------------
// A[m][k] hi/lo bf16 row-major; Bt[n][k] hi/lo bf16 (K contiguous) -> col-major B for mma.
// CTA 128x128, 8 warps each 64x32, K staged 32 per iteration.
#define KC 32
#define SSTR 40   // padded smem row stride in bf16 elems (80B)

__device__ __forceinline__ void mma16816(float* c, const uint32_t* a, const uint32_t* b) {
    asm volatile(
        "mma.sync.aligned.m16n8k16.row.col.f32.bf16.bf16.f32 "
        "{%0,%1,%2,%3}, {%4,%5,%6,%7}, {%8,%9}, {%0,%1,%2,%3};"
        : "+f"(c[0]), "+f"(c[1]), "+f"(c[2]), "+f"(c[3])
        : "r"(a[0]), "r"(a[1]), "r"(a[2]), "r"(a[3]), "r"(b[0]), "r"(b[1]));
}

template <bool ADD_RES>
__global__ __launch_bounds__(256)
void gemm_mma(const __nv_bfloat16* __restrict__ Ah, const __nv_bfloat16* __restrict__ Al,
              const __nv_bfloat16* __restrict__ Bh, const __nv_bfloat16* __restrict__ Bl,
              const float* __restrict__ bias, const float* __restrict__ res,
              float* __restrict__ C)
{
    __shared__ __nv_bfloat16 sAh[128 * SSTR];
    __shared__ __nv_bfloat16 sAl[128 * SSTR];
    __shared__ __nv_bfloat16 sBh[128 * SSTR];
    __shared__ __nv_bfloat16 sBl[128 * SSTR];

    const int t = threadIdx.x;
    const int wid = t >> 5, lane = t & 31;
    const int wm = (wid >> 2) * 64;   // warp row offset (0 / 64)
    const int wn = (wid & 3) * 32;    // warp col offset (0..96)
    const int lr = lane >> 2;         // 0..7
    const int lc = (lane & 3) * 2;    // 0,2,4,6
    const int m0 = blockIdx.y * 128;
    const int n0 = blockIdx.x * 128;

    float acc[4][4][4];
#pragma unroll
    for (int mi = 0; mi < 4; mi++)
#pragma unroll
        for (int ni = 0; ni < 4; ni++)
#pragma unroll
            for (int r = 0; r < 4; r++) acc[mi][ni][r] = 0.f;

    for (int k0 = 0; k0 < EMB; k0 += KC) {
        __syncthreads();
        // load 4 tiles of 128 x 32 bf16 (each: 512 uint4, 2 per thread)
#pragma unroll
        for (int u = 0; u < 2; u++) {
            int idx = t + u * 256;
            int r = idx >> 2;
            int c8 = (idx & 3) * 8;
            uint32_t so = (uint32_t)(r * SSTR + c8);
            *(uint4*)&sAh[so] = *(const uint4*)&Ah[(size_t)(m0 + r) * EMB + k0 + c8];
            *(uint4*)&sAl[so] = *(const uint4*)&Al[(size_t)(m0 + r) * EMB + k0 + c8];
            *(uint4*)&sBh[so] = *(const uint4*)&Bh[(size_t)(n0 + r) * EMB + k0 + c8];
            *(uint4*)&sBl[so] = *(const uint4*)&Bl[(size_t)(n0 + r) * EMB + k0 + c8];
        }
        __syncthreads();

#pragma unroll
        for (int ks = 0; ks < 2; ks++) {
            const int kk = ks * 16;
            uint32_t ah[4][4], al[4][4], bh[4][2], bl[4][2];
#pragma unroll
            for (int mi = 0; mi < 4; mi++) {
                const int ra = wm + mi * 16 + lr;
                ah[mi][0] = *(const uint32_t*)&sAh[(ra    ) * SSTR + kk + lc];
                ah[mi][1] = *(const uint32_t*)&sAh[(ra + 8) * SSTR + kk + lc];
                ah[mi][2] = *(const uint32_t*)&sAh[(ra    ) * SSTR + kk + lc + 8];
                ah[mi][3] = *(const uint32_t*)&sAh[(ra + 8) * SSTR + kk + lc + 8];
            }
#pragma unroll
            for (int ni = 0; ni < 4; ni++) {
                const int rb = wn + ni * 8 + lr;
                bh[ni][0] = *(const uint32_t*)&sBh[rb * SSTR + kk + lc];
                bh[ni][1] = *(const uint32_t*)&sBh[rb * SSTR + kk + lc + 8];
            }
            // pass 0: Ah * Bh
#pragma unroll
            for (int mi = 0; mi < 4; mi++)
#pragma unroll
                for (int ni = 0; ni < 4; ni++) mma16816(acc[mi][ni], ah[mi], bh[ni]);
            // pass 1: Ah * Bl
#pragma unroll
            for (int ni = 0; ni < 4; ni++) {
                const int rb = wn + ni * 8 + lr;
                bl[ni][0] = *(const uint32_t*)&sBl[rb * SSTR + kk + lc];
                bl[ni][1] = *(const uint32_t*)&sBl[rb * SSTR + kk + lc + 8];
            }
#pragma unroll
            for (int mi = 0; mi < 4; mi++)
#pragma unroll
                for (int ni = 0; ni < 4; ni++) mma16816(acc[mi][ni], ah[mi], bl[ni]);
            // pass 2: Al * Bh
#pragma unroll
            for (int mi = 0; mi < 4; mi++) {
                const int ra = wm + mi * 16 + lr;
                al[mi][0] = *(const uint32_t*)&sAl[(ra    ) * SSTR + kk + lc];
                al[mi][1] = *(const uint32_t*)&sAl[(ra + 8) * SSTR + kk + lc];
                al[mi][2] = *(const uint32_t*)&sAl[(ra    ) * SSTR + kk + lc + 8];
                al[mi][3] = *(const uint32_t*)&sAl[(ra + 8) * SSTR + kk + lc + 8];
            }
#pragma unroll
            for (int mi = 0; mi < 4; mi++)
#pragma unroll
                for (int ni = 0; ni < 4; ni++) mma16816(acc[mi][ni], al[mi], bh[ni]);
        }
    }

    // epilogue: bias (+residual), direct to gmem
#pragma unroll
    for (int mi = 0; mi < 4; mi++) {
        const int row0 = m0 + wm + mi * 16 + lr;
        const int row1 = row0 + 8;
#pragma unroll
        for (int ni = 0; ni < 4; ni++) {
            const int col = n0 + wn + ni * 8 + lc;
            float2 bs = *(const float2*)&bias[col];
            float2 o0, o1;
            o0.x = acc[mi][ni][0] + bs.x;
            o0.y = acc[mi][ni][1] + bs.y;
            o1.x = acc[mi][ni][2] + bs.x;
            o1.y = acc[mi][ni][3] + bs.y;
            if (ADD_RES) {
                float2 r0 = *(const float2*)&res[(size_t)row0 * EMB + col];
                float2 r1 = *(const float2*)&res[(size_t)row1 * EMB + col];
                o0.x += r0.x; o0.y += r0.y;
                o1.x += r1.x; o1.y += r1.y;
            }
            *(float2*)&C[(size_t)row0 * EMB + col] = o0;
            *(float2*)&C[(size_t)row1 * EMB + col] = o1;
        }
    }
}

// ---------------- attention: flash-style fp32 (unchanged from passing R3) ----------------
#define ASTR 68

__global__ __launch_bounds__(256)
void attn_kernel(const float* __restrict__ Q, const float* __restrict__ K,
                 const float* __restrict__ V, float* __restrict__ O)
{
    extern __shared__ float sm[];
    float* Qs = sm;
    float* Ks = sm + 64 * ASTR;
    float* Vs = sm + 2 * 64 * ASTR;

    const int t = threadIdx.x;
    const int ty = t >> 4;
    const int tx = t & 15;
    const int q0 = blockIdx.x * 64;
    const int h = blockIdx.y;
    const int b = blockIdx.z;

    const float* Qb = Q + (size_t)b * SEQ * EMB + h * HD;
    const float* Kb = K + (size_t)b * SEQ * EMB + h * HD;
    const float* Vb = V + (size_t)b * SEQ * EMB + h * HD;

#pragma unroll
    for (int u = 0; u < 4; u++) {
        int lin = t + u * 256;
        int r = lin >> 4;
        int c4 = (lin & 15) * 4;
        float4 v = *(const float4*)&Qb[(size_t)(q0 + r) * EMB + c4];
        Qs[(c4 + 0) * ASTR + r] = v.x;
        Qs[(c4 + 1) * ASTR + r] = v.y;
        Qs[(c4 + 2) * ASTR + r] = v.z;
        Qs[(c4 + 3) * ASTR + r] = v.w;
    }

    float m_[4], l_[4], o_[4][4];
#pragma unroll
    for (int i = 0; i < 4; i++) {
        m_[i] = -1e30f;
        l_[i] = 0.f;
#pragma unroll
        for (int j = 0; j < 4; j++) o_[i][j] = 0.f;
    }

    for (int kv0 = 0; kv0 < SEQ; kv0 += 64) {
        __syncthreads();
#pragma unroll
        for (int u = 0; u < 4; u++) {
            int lin = t + u * 256;
            int r = lin >> 4;
            int c4 = (lin & 15) * 4;
            float4 kv = *(const float4*)&Kb[(size_t)(kv0 + r) * EMB + c4];
            Ks[(c4 + 0) * ASTR + r] = kv.x;
            Ks[(c4 + 1) * ASTR + r] = kv.y;
            Ks[(c4 + 2) * ASTR + r] = kv.z;
            Ks[(c4 + 3) * ASTR + r] = kv.w;
            float4 vv = *(const float4*)&Vb[(size_t)(kv0 + r) * EMB + c4];
            *(float4*)&Vs[r * ASTR + c4] = vv;
        }
        __syncthreads();

        float s[4][4];
#pragma unroll
        for (int i = 0; i < 4; i++)
#pragma unroll
            for (int j = 0; j < 4; j++) s[i][j] = 0.f;

#pragma unroll 16
        for (int d = 0; d < 64; d++) {
            float4 a = *(float4*)&Qs[d * ASTR + ty * 4];
            float4 bb = *(float4*)&Ks[d * ASTR + tx * 4];
            float av[4] = {a.x, a.y, a.z, a.w};
            float bv[4] = {bb.x, bb.y, bb.z, bb.w};
#pragma unroll
            for (int i = 0; i < 4; i++)
#pragma unroll
                for (int j = 0; j < 4; j++) s[i][j] += av[i] * bv[j];
        }

        float p[4][4], alpha[4];
#pragma unroll
        for (int i = 0; i < 4; i++) {
            float rm = s[i][0];
#pragma unroll
            for (int j = 1; j < 4; j++) rm = fmaxf(rm, s[i][j]);
            rm *= 0.125f;
#pragma unroll
            for (int off = 1; off < 16; off <<= 1)
                rm = fmaxf(rm, __shfl_xor_sync(0xffffffffu, rm, off));
            float mnew = fmaxf(m_[i], rm);
            alpha[i] = __expf(m_[i] - mnew);
            float rs = 0.f;
#pragma unroll
            for (int j = 0; j < 4; j++) {
                p[i][j] = __expf(s[i][j] * 0.125f - mnew);
                rs += p[i][j];
            }
#pragma unroll
            for (int off = 1; off < 16; off <<= 1)
                rs += __shfl_xor_sync(0xffffffffu, rs, off);
            l_[i] = l_[i] * alpha[i] + rs;
            m_[i] = mnew;
#pragma unroll
            for (int j = 0; j < 4; j++) o_[i][j] *= alpha[i];
        }

        __syncthreads();
#pragma unroll
        for (int i = 0; i < 4; i++)
#pragma unroll
            for (int j = 0; j < 4; j++)
                Ks[(tx * 4 + j) * ASTR + (ty * 4 + i)] = p[i][j];
        __syncthreads();

#pragma unroll 16
        for (int j = 0; j < 64; j++) {
            float4 a = *(float4*)&Ks[j * ASTR + ty * 4];
            float4 bv = *(float4*)&Vs[j * ASTR + tx * 4];
            float av[4] = {a.x, a.y, a.z, a.w};
            float vv[4] = {bv.x, bv.y, bv.z, bv.w};
#pragma unroll
            for (int i = 0; i < 4; i++)
#pragma unroll
                for (int j2 = 0; j2 < 4; j2++) o_[i][j2] += av[i] * vv[j2];
        }
    }

#pragma unroll
    for (int i = 0; i < 4; i++) {
        float inv = 1.f / l_[i];
        int row = b * SEQ + q0 + ty * 4 + i;
        float4 o;
        o.x = o_[i][0] * inv;
        o.y = o_[i][1] * inv;
        o.z = o_[i][2] * inv;
        o.w = o_[i][3] * inv;
        *(float4*)&O[(size_t)row * EMB + h * HD + tx * 4] = o;
    }
}

// ---------------- LayerNorm ----------------
__global__ __launch_bounds__(256)
void layernorm_kernel(const float* __restrict__ X, const float* __restrict__ gamma,
                      const float* __restrict__ beta, float* __restrict__ out)
{
    __shared__ float ssum[256];
    __shared__ float ssq[256];
    const int row = blockIdx.x;
    const int t = threadIdx.x;
    const float* x = X + (size_t)row * EMB;

    float4 v = *(const float4*)&x[t * 4];
    ssum[t] = v.x + v.y + v.z + v.w;
    ssq[t] = v.x * v.x + v.y * v.y + v.z * v.z + v.w * v.w;
    __syncthreads();
#pragma unroll
    for (int off = 128; off > 0; off >>= 1) {
        if (t < off) {
            ssum[t] += ssum[t + off];
            ssq[t] += ssq[t + off];
        }
        __syncthreads();
    }
    const float mu = ssum[0] * (1.f / EMB);
    const float var = ssq[0] * (1.f / EMB) - mu * mu;
    const float rs = rsqrtf(var + 1e-5f);

    float4 g = *(const float4*)&gamma[t * 4];
    float4 be = *(const float4*)&beta[t * 4];
    float4 o;
    o.x = (v.x - mu) * rs * g.x + be.x;
    o.y = (v.y - mu) * rs * g.y + be.y;
    o.z = (v.z - mu) * rs * g.z + be.z;
    o.w = (v.w - mu) * rs * g.w + be.w;
    *(float4*)&out[(size_t)row * EMB + t * 4] = o;
}

// ---------------- launch ----------------
extern "C" void kernel_launch(void* const* d_in, const int* in_sizes, int n_in,
                              void* d_out, int out_size)
{
    const float* query = (const float*)d_in[0];
    const float* key   = (const float*)d_in[1];
    const float* value = (const float*)d_in[2];
    const float* Wq    = (const float*)d_in[3];
    const float* bq    = (const float*)d_in[4];
    const float* Wk    = (const float*)d_in[5];
    const float* bk    = (const float*)d_in[6];
    const float* Wv    = (const float*)d_in[7];
    const float* bv    = (const float*)d_in[8];
    const float* Wo    = (const float*)d_in[9];
    const float* bo    = (const float*)d_in[10];
    const float* ln_g  = (const float*)d_in[11];
    const float* ln_b  = (const float*)d_in[12];
    float* out = (float*)d_out;

    float *Qp, *Kp, *Vp, *ATTp, *TMPp;
    cudaGetSymbolAddress((void**)&Qp, g_Q);
    cudaGetSymbolAddress((void**)&Kp, g_K);
    cudaGetSymbolAddress((void**)&Vp, g_V);
    cudaGetSymbolAddress((void**)&ATTp, g_ATT);
    cudaGetSymbolAddress((void**)&TMPp, g_TMP);

    __nv_bfloat16 *qh, *ql, *kh, *kl, *vh, *vl, *oh, *ol;
    __nv_bfloat16 *wqh, *wql, *wkh, *wkl, *wvh, *wvl, *woh, *wol;
    cudaGetSymbolAddress((void**)&qh, g_qh);  cudaGetSymbolAddress((void**)&ql, g_ql);
    cudaGetSymbolAddress((void**)&kh, g_kh);  cudaGetSymbolAddress((void**)&kl, g_kl);
    cudaGetSymbolAddress((void**)&vh, g_vh);  cudaGetSymbolAddress((void**)&vl, g_vl);
    cudaGetSymbolAddress((void**)&oh, g_oh);  cudaGetSymbolAddress((void**)&ol, g_ol);
    cudaGetSymbolAddress((void**)&wqh, g_wqh); cudaGetSymbolAddress((void**)&wql, g_wql);
    cudaGetSymbolAddress((void**)&wkh, g_wkh); cudaGetSymbolAddress((void**)&wkl, g_wkl);
    cudaGetSymbolAddress((void**)&wvh, g_wvh); cudaGetSymbolAddress((void**)&wvl, g_wvl);
    cudaGetSymbolAddress((void**)&woh, g_woh); cudaGetSymbolAddress((void**)&wol, g_wol);

    const int smem_attn = 3 * 64 * ASTR * sizeof(float);
    static bool attr_set = false;
    if (!attr_set) {
        cudaFuncSetAttribute(attn_kernel, cudaFuncAttributeMaxDynamicSharedMemorySize, smem_attn);
        attr_set = true;
    }

    // 1. split inputs to bf16 hi/lo
    const int split_grid = (int)(NELEM / (256 * 4));  // 4096
    fsplit<<<split_grid, 256>>>(query, qh, ql);
    fsplit<<<split_grid, 256>>>(key,   kh, kl);
    fsplit<<<split_grid, 256>>>(value, vh, vl);

    // 2. transpose + split weights to [N, K] K-major bf16 hi/lo
    dim3 wgrid(EMB / 32, EMB / 32);
    dim3 wblk(32, 8);
    wsplitT<<<wgrid, wblk>>>(Wq, wqh, wql);
    wsplitT<<<wgrid, wblk>>>(Wk, wkh, wkl);
    wsplitT<<<wgrid, wblk>>>(Wv, wvh, wvl);
    wsplitT<<<wgrid, wblk>>>(Wo, woh, wol);

    // 3. tensor-core (mma.sync) projections
    dim3 ggrid(EMB / 128, MROWS / 128);  // (8, 32)
    gemm_mma<false><<<ggrid, 256>>>(qh, ql, wqh, wql, bq, nullptr, Qp);
    gemm_mma<false><<<ggrid, 256>>>(kh, kl, wkh, wkl, bk, nullptr, Kp);
    gemm_mma<false><<<ggrid, 256>>>(vh, vl, wvh, wvl, bv, nullptr, Vp);

    // 4. attention
    dim3 attn_grid(SEQ / 64, NH, BATCH);
    attn_kernel<<<attn_grid, 256, smem_attn>>>(Qp, Kp, Vp, ATTp);

    // 5. output projection + residual (mma.sync)
    fsplit<<<split_grid, 256>>>(ATTp, oh, ol);
    gemm_mma<true><<<ggrid, 256>>>(oh, ol, woh, wol, bo, query, TMPp);

    // 6. layernorm
    layernorm_kernel<<<MROWS, 256>>>(TMPp, ln_g, ln_b, out);
}

// round 7
// speedup vs baseline: 1.7135x; 1.4710x over previous
#include <cuda_runtime.h>
#include <cuda_bf16.h>
#include <math.h>
#include <stdint.h>

#define BATCH 2
#define SEQ 2048
#define EMB 1024
#define NH 16
#define HD 64
#define MROWS (BATCH * SEQ)   // 4096
#define NELEM ((size_t)MROWS * EMB)

// ---------------- device scratch (no allocations allowed) ----------------
// g_Q/g_K/g_V are reused as bf16 hi/lo pairs (hi = first NELEM bf16, lo = second)
__device__ float g_Q[NELEM];
__device__ float g_K[NELEM];
__device__ float g_V[NELEM];
__device__ float g_TMP[NELEM];

__device__ __nv_bfloat16 g_qh[NELEM], g_ql[NELEM];
__device__ __nv_bfloat16 g_kh[NELEM], g_kl[NELEM];
__device__ __nv_bfloat16 g_vh[NELEM], g_vl[NELEM];
__device__ __nv_bfloat16 g_oh[NELEM], g_ol[NELEM];
__device__ __nv_bfloat16 g_wqh[EMB*EMB], g_wql[EMB*EMB];
__device__ __nv_bfloat16 g_wkh[EMB*EMB], g_wkl[EMB*EMB];
__device__ __nv_bfloat16 g_wvh[EMB*EMB], g_wvl[EMB*EMB];
__device__ __nv_bfloat16 g_woh[EMB*EMB], g_wol[EMB*EMB];

// ---------------- helpers ----------------
__device__ __forceinline__ void mma16816(float* c, const uint32_t* a, const uint32_t* b) {
    asm volatile(
        "mma.sync.aligned.m16n8k16.row.col.f32.bf16.bf16.f32 "
        "{%0,%1,%2,%3}, {%4,%5,%6,%7}, {%8,%9}, {%0,%1,%2,%3};"
        : "+f"(c[0]), "+f"(c[1]), "+f"(c[2]), "+f"(c[3])
        : "r"(a[0]), "r"(a[1]), "r"(a[2]), "r"(a[3]), "r"(b[0]), "r"(b[1]));
}

// pack two f32 into bf16x2: low half = x, high half = y
__device__ __forceinline__ uint32_t packbf(float x, float y) {
    uint32_t r;
    asm("cvt.rn.bf16x2.f32 %0, %1, %2;" : "=r"(r) : "f"(y), "f"(x));
    return r;
}

// ---------------- fp32 -> bf16 hi/lo split ----------------
__global__ __launch_bounds__(256)
void fsplit(const float* __restrict__ x, __nv_bfloat16* __restrict__ hi,
            __nv_bfloat16* __restrict__ lo)
{
    size_t i = ((size_t)blockIdx.x * 256 + threadIdx.x) * 4;
    float4 v = *(const float4*)(x + i);
    float vv[4] = {v.x, v.y, v.z, v.w};
    uint32_t ph[2], pl[2];
#pragma unroll
    for (int p = 0; p < 2; p++) {
        uint32_t hp = packbf(vv[2*p], vv[2*p+1]);
        float h0 = __uint_as_float(hp << 16);
        float h1 = __uint_as_float(hp & 0xffff0000u);
        ph[p] = hp;
        pl[p] = packbf(vv[2*p] - h0, vv[2*p+1] - h1);
    }
    *(uint2*)(hi + i) = make_uint2(ph[0], ph[1]);
    *(uint2*)(lo + i) = make_uint2(pl[0], pl[1]);
}

// ---------------- W[K,N] -> Wt[N,K] transpose + hi/lo split ----------------
__global__ __launch_bounds__(256)
void wsplitT(const float* __restrict__ W, __nv_bfloat16* __restrict__ th,
             __nv_bfloat16* __restrict__ tl)
{
    __shared__ float tile[32][33];
    const int n0 = blockIdx.x * 32, k0 = blockIdx.y * 32;
    const int tx = threadIdx.x, ty0 = threadIdx.y;  // (32, 8)
#pragma unroll
    for (int i = 0; i < 4; i++) {
        int ty = ty0 + i * 8;
        tile[ty][tx] = W[(size_t)(k0 + ty) * EMB + n0 + tx];
    }
    __syncthreads();
#pragma unroll
    for (int i = 0; i < 4; i++) {
        int ty = ty0 + i * 8;
        float x = tile[tx][ty];  // W[k0+tx][n0+ty]
        __nv_bfloat16 h = __float2bfloat16(x);
        __nv_bfloat16 l = __float2bfloat16(x - __bfloat162float(h));
        th[(size_t)(n0 + ty) * EMB + k0 + tx] = h;
        tl[(size_t)(n0 + ty) * EMB + k0 + tx] = l;
    }
}

// ---------------- mma.sync bf16 split GEMM ----------------
// MODE 0: fp32 out + bias.  MODE 1: fp32 out + bias + residual.
// MODE 2: bf16 hi/lo out, val = (acc + bias) * scale.
#define KC 32
#define SSTR 40

template <int MODE>
__global__ __launch_bounds__(256)
void gemm_mma(const __nv_bfloat16* __restrict__ Ah, const __nv_bfloat16* __restrict__ Al,
              const __nv_bfloat16* __restrict__ Bh, const __nv_bfloat16* __restrict__ Bl,
              const float* __restrict__ bias, const float* __restrict__ res,
              float* __restrict__ Cf, __nv_bfloat16* __restrict__ Ch,
              __nv_bfloat16* __restrict__ Cl, float scale)
{
    __shared__ __nv_bfloat16 sAh[128 * SSTR];
    __shared__ __nv_bfloat16 sAl[128 * SSTR];
    __shared__ __nv_bfloat16 sBh[128 * SSTR];
    __shared__ __nv_bfloat16 sBl[128 * SSTR];

    const int t = threadIdx.x;
    const int wid = t >> 5, lane = t & 31;
    const int wm = (wid >> 2) * 64;
    const int wn = (wid & 3) * 32;
    const int lr = lane >> 2;
    const int lc = (lane & 3) * 2;
    const int m0 = blockIdx.y * 128;
    const int n0 = blockIdx.x * 128;

    float acc[4][4][4];
#pragma unroll
    for (int mi = 0; mi < 4; mi++)
#pragma unroll
        for (int ni = 0; ni < 4; ni++)
#pragma unroll
            for (int r = 0; r < 4; r++) acc[mi][ni][r] = 0.f;

    for (int k0 = 0; k0 < EMB; k0 += KC) {
        __syncthreads();
#pragma unroll
        for (int u = 0; u < 2; u++) {
            int idx = t + u * 256;
            int r = idx >> 2;
            int c8 = (idx & 3) * 8;
            uint32_t so = (uint32_t)(r * SSTR + c8);
            *(uint4*)&sAh[so] = *(const uint4*)&Ah[(size_t)(m0 + r) * EMB + k0 + c8];
            *(uint4*)&sAl[so] = *(const uint4*)&Al[(size_t)(m0 + r) * EMB + k0 + c8];
            *(uint4*)&sBh[so] = *(const uint4*)&Bh[(size_t)(n0 + r) * EMB + k0 + c8];
            *(uint4*)&sBl[so] = *(const uint4*)&Bl[(size_t)(n0 + r) * EMB + k0 + c8];
        }
        __syncthreads();

#pragma unroll
        for (int ks = 0; ks < 2; ks++) {
            const int kk = ks * 16;
            uint32_t ah[4][4], al[4][4], bh[4][2], bl[4][2];
#pragma unroll
            for (int mi = 0; mi < 4; mi++) {
                const int ra = wm + mi * 16 + lr;
                ah[mi][0] = *(const uint32_t*)&sAh[(ra    ) * SSTR + kk + lc];
                ah[mi][1] = *(const uint32_t*)&sAh[(ra + 8) * SSTR + kk + lc];
                ah[mi][2] = *(const uint32_t*)&sAh[(ra    ) * SSTR + kk + lc + 8];
                ah[mi][3] = *(const uint32_t*)&sAh[(ra + 8) * SSTR + kk + lc + 8];
            }
#pragma unroll
            for (int ni = 0; ni < 4; ni++) {
                const int rb = wn + ni * 8 + lr;
                bh[ni][0] = *(const uint32_t*)&sBh[rb * SSTR + kk + lc];
                bh[ni][1] = *(const uint32_t*)&sBh[rb * SSTR + kk + lc + 8];
            }
#pragma unroll
            for (int mi = 0; mi < 4; mi++)
#pragma unroll
                for (int ni = 0; ni < 4; ni++) mma16816(acc[mi][ni], ah[mi], bh[ni]);
#pragma unroll
            for (int ni = 0; ni < 4; ni++) {
                const int rb = wn + ni * 8 + lr;
                bl[ni][0] = *(const uint32_t*)&sBl[rb * SSTR + kk + lc];
                bl[ni][1] = *(const uint32_t*)&sBl[rb * SSTR + kk + lc + 8];
            }
#pragma unroll
            for (int mi = 0; mi < 4; mi++)
#pragma unroll
                for (int ni = 0; ni < 4; ni++) mma16816(acc[mi][ni], ah[mi], bl[ni]);
#pragma unroll
            for (int mi = 0; mi < 4; mi++) {
                const int ra = wm + mi * 16 + lr;
                al[mi][0] = *(const uint32_t*)&sAl[(ra    ) * SSTR + kk + lc];
                al[mi][1] = *(const uint32_t*)&sAl[(ra + 8) * SSTR + kk + lc];
                al[mi][2] = *(const uint32_t*)&sAl[(ra    ) * SSTR + kk + lc + 8];
                al[mi][3] = *(const uint32_t*)&sAl[(ra + 8) * SSTR + kk + lc + 8];
            }
#pragma unroll
            for (int mi = 0; mi < 4; mi++)
#pragma unroll
                for (int ni = 0; ni < 4; ni++) mma16816(acc[mi][ni], al[mi], bh[ni]);
        }
    }

#pragma unroll
    for (int mi = 0; mi < 4; mi++) {
        const int row0 = m0 + wm + mi * 16 + lr;
        const int row1 = row0 + 8;
#pragma unroll
        for (int ni = 0; ni < 4; ni++) {
            const int col = n0 + wn + ni * 8 + lc;
            float2 bs = *(const float2*)&bias[col];
            if (MODE == 2) {
                float v00 = (acc[mi][ni][0] + bs.x) * scale;
                float v01 = (acc[mi][ni][1] + bs.y) * scale;
                float v10 = (acc[mi][ni][2] + bs.x) * scale;
                float v11 = (acc[mi][ni][3] + bs.y) * scale;
                uint32_t h0 = packbf(v00, v01);
                uint32_t h1 = packbf(v10, v11);
                uint32_t l0 = packbf(v00 - __uint_as_float(h0 << 16),
                                     v01 - __uint_as_float(h0 & 0xffff0000u));
                uint32_t l1 = packbf(v10 - __uint_as_float(h1 << 16),
                                     v11 - __uint_as_float(h1 & 0xffff0000u));
                *(uint32_t*)&Ch[(size_t)row0 * EMB + col] = h0;
                *(uint32_t*)&Cl[(size_t)row0 * EMB + col] = l0;
                *(uint32_t*)&Ch[(size_t)row1 * EMB + col] = h1;
                *(uint32_t*)&Cl[(size_t)row1 * EMB + col] = l1;
            } else {
                float2 o0, o1;
                o0.x = acc[mi][ni][0] + bs.x;
                o0.y = acc[mi][ni][1] + bs.y;
                o1.x = acc[mi][ni][2] + bs.x;
                o1.y = acc[mi][ni][3] + bs.y;
                if (MODE == 1) {
                    float2 r0 = *(const float2*)&res[(size_t)row0 * EMB + col];
                    float2 r1 = *(const float2*)&res[(size_t)row1 * EMB + col];
                    o0.x += r0.x; o0.y += r0.y;
                    o1.x += r1.x; o1.y += r1.y;
                }
                *(float2*)&Cf[(size_t)row0 * EMB + col] = o0;
                *(float2*)&Cf[(size_t)row1 * EMB + col] = o1;
            }
        }
    }
}

// ---------------- attention: FA2-style, split-bf16 mma.sync ----------------
// CTA: 128 q-rows, 8 warps x 16 rows. KV blocks of 64. Q pre-scaled by 1/8.
#define SK 72   // smem stride in bf16 (144B = 36 words; 36n%32=4n -> conflict-free b-frags)

__global__ __launch_bounds__(256)
void attn_mma(const __nv_bfloat16* __restrict__ Qh, const __nv_bfloat16* __restrict__ Ql,
              const __nv_bfloat16* __restrict__ Kh, const __nv_bfloat16* __restrict__ Kl,
              const __nv_bfloat16* __restrict__ Vh, const __nv_bfloat16* __restrict__ Vl,
              __nv_bfloat16* __restrict__ Oh, __nv_bfloat16* __restrict__ Ol)
{
    __shared__ __nv_bfloat16 sKh[64 * SK], sKl[64 * SK];
    __shared__ __nv_bfloat16 sVh[64 * SK], sVl[64 * SK];   // transposed: [d][j]

    const int t = threadIdx.x;
    const int wid = t >> 5, lane = t & 31;
    const int lr = lane >> 2;          // group id 0..7
    const int lc = (lane & 3) * 2;     // 0,2,4,6
    const int q0 = blockIdx.x * 128;
    const int h = blockIdx.y;
    const int b = blockIdx.z;
    const int wr = wid * 16;           // warp's q-row offset in tile

    // ---- load Q fragments once (loop-invariant), pre-scaled in projection ----
    uint32_t qah[4][4], qal[4][4];
    {
        const size_t base0 = (size_t)(b * SEQ + q0 + wr + lr) * EMB + h * HD;
        const size_t base1 = base0 + (size_t)8 * EMB;
#pragma unroll
        for (int ks = 0; ks < 4; ks++) {
            const int c0 = ks * 16 + lc;
            qah[ks][0] = *(const uint32_t*)&Qh[base0 + c0];
            qah[ks][1] = *(const uint32_t*)&Qh[base1 + c0];
            qah[ks][2] = *(const uint32_t*)&Qh[base0 + c0 + 8];
            qah[ks][3] = *(const uint32_t*)&Qh[base1 + c0 + 8];
            qal[ks][0] = *(const uint32_t*)&Ql[base0 + c0];
            qal[ks][1] = *(const uint32_t*)&Ql[base1 + c0];
            qal[ks][2] = *(const uint32_t*)&Ql[base0 + c0 + 8];
            qal[ks][3] = *(const uint32_t*)&Ql[base1 + c0 + 8];
        }
    }

    float m0 = -1e30f, m1 = -1e30f, l0 = 0.f, l1 = 0.f;
    float co[8][4];
#pragma unroll
    for (int d = 0; d < 8; d++)
#pragma unroll
        for (int r = 0; r < 4; r++) co[d][r] = 0.f;

    for (int kv0 = 0; kv0 < SEQ; kv0 += 64) {
        __syncthreads();
        // ---- load K (natural) and V (transposed) tiles, hi+lo ----
#pragma unroll
        for (int u = 0; u < 2; u++) {
            int idx = t + u * 256;          // 0..511
            int j = idx >> 3;               // kv row 0..63
            int d0 = (idx & 7) * 8;         // dim 0..56
            size_t g = (size_t)(b * SEQ + kv0 + j) * EMB + h * HD + d0;
            uint4 kh4 = *(const uint4*)&Kh[g];
            uint4 kl4 = *(const uint4*)&Kl[g];
            *(uint4*)&sKh[j * SK + d0] = kh4;
            *(uint4*)&sKl[j * SK + d0] = kl4;
            uint4 vh4 = *(const uint4*)&Vh[g];
            uint4 vl4 = *(const uint4*)&Vl[g];
            const uint32_t* vh32 = (const uint32_t*)&vh4;
            const uint32_t* vl32 = (const uint32_t*)&vl4;
#pragma unroll
            for (int e = 0; e < 4; e++) {
                ((unsigned short*)sVh)[(d0 + 2*e    ) * SK + j] = (unsigned short)(vh32[e] & 0xffff);
                ((unsigned short*)sVh)[(d0 + 2*e + 1) * SK + j] = (unsigned short)(vh32[e] >> 16);
                ((unsigned short*)sVl)[(d0 + 2*e    ) * SK + j] = (unsigned short)(vl32[e] & 0xffff);
                ((unsigned short*)sVl)[(d0 + 2*e + 1) * SK + j] = (unsigned short)(vl32[e] >> 16);
            }
        }
        __syncthreads();

        // ---- S = Qs @ K^T (3-pass split) ----
        float cs[8][4];
#pragma unroll
        for (int n = 0; n < 8; n++)
#pragma unroll
            for (int r = 0; r < 4; r++) cs[n][r] = 0.f;

#pragma unroll
        for (int ks = 0; ks < 4; ks++) {
            const int kk = ks * 16 + lc;
#pragma unroll
            for (int nt = 0; nt < 8; nt++) {
                const int rb = nt * 8 + lr;
                uint32_t bh[2], bl[2];
                bh[0] = *(const uint32_t*)&sKh[rb * SK + kk];
                bh[1] = *(const uint32_t*)&sKh[rb * SK + kk + 8];
                mma16816(cs[nt], qah[ks], bh);
                bl[0] = *(const uint32_t*)&sKl[rb * SK + kk];
                bl[1] = *(const uint32_t*)&sKl[rb * SK + kk + 8];
                mma16816(cs[nt], qah[ks], bl);
                mma16816(cs[nt], qal[ks], bh);
            }
        }

        // ---- online softmax (scores already scaled by 1/8 via Q) ----
        float rm0 = cs[0][0], rm1 = cs[0][2];
#pragma unroll
        for (int n = 0; n < 8; n++) {
            rm0 = fmaxf(rm0, fmaxf(cs[n][0], cs[n][1]));
            rm1 = fmaxf(rm1, fmaxf(cs[n][2], cs[n][3]));
        }
        rm0 = fmaxf(rm0, __shfl_xor_sync(0xffffffffu, rm0, 1));
        rm0 = fmaxf(rm0, __shfl_xor_sync(0xffffffffu, rm0, 2));
        rm1 = fmaxf(rm1, __shfl_xor_sync(0xffffffffu, rm1, 1));
        rm1 = fmaxf(rm1, __shfl_xor_sync(0xffffffffu, rm1, 2));
        float nm0 = fmaxf(m0, rm0), nm1 = fmaxf(m1, rm1);
        float al0 = __expf(m0 - nm0), al1 = __expf(m1 - nm1);
        float sum0 = 0.f, sum1 = 0.f;
#pragma unroll
        for (int n = 0; n < 8; n++) {
            cs[n][0] = __expf(cs[n][0] - nm0);
            cs[n][1] = __expf(cs[n][1] - nm0);
            cs[n][2] = __expf(cs[n][2] - nm1);
            cs[n][3] = __expf(cs[n][3] - nm1);
            sum0 += cs[n][0] + cs[n][1];
            sum1 += cs[n][2] + cs[n][3];
        }
        sum0 += __shfl_xor_sync(0xffffffffu, sum0, 1);
        sum0 += __shfl_xor_sync(0xffffffffu, sum0, 2);
        sum1 += __shfl_xor_sync(0xffffffffu, sum1, 1);
        sum1 += __shfl_xor_sync(0xffffffffu, sum1, 2);
        l0 = l0 * al0 + sum0;  m0 = nm0;
        l1 = l1 * al1 + sum1;  m1 = nm1;
#pragma unroll
        for (int d = 0; d < 8; d++) {
            co[d][0] *= al0; co[d][1] *= al0;
            co[d][2] *= al1; co[d][3] *= al1;
        }

        // ---- O += P @ V (3-pass split; P packed from cs in registers) ----
#pragma unroll
        for (int ks = 0; ks < 4; ks++) {
            uint32_t ph[4], pl[4];
#pragma unroll
            for (int half = 0; half < 2; half++) {
                const float* c0 = cs[2 * ks + half];
                uint32_t hA = packbf(c0[0], c0[1]);
                uint32_t hB = packbf(c0[2], c0[3]);
                ph[2 * half    ] = hA;
                ph[2 * half + 1] = hB;
                pl[2 * half    ] = packbf(c0[0] - __uint_as_float(hA << 16),
                                          c0[1] - __uint_as_float(hA & 0xffff0000u));
                pl[2 * half + 1] = packbf(c0[2] - __uint_as_float(hB << 16),
                                          c0[3] - __uint_as_float(hB & 0xffff0000u));
            }
            const int kk = ks * 16 + lc;
#pragma unroll
            for (int dt = 0; dt < 8; dt++) {
                const int rb = dt * 8 + lr;
                uint32_t bh[2], bl[2];
                bh[0] = *(const uint32_t*)&sVh[rb * SK + kk];
                bh[1] = *(const uint32_t*)&sVh[rb * SK + kk + 8];
                mma16816(co[dt], ph, bh);
                mma16816(co[dt], pl, bh);
                bl[0] = *(const uint32_t*)&sVl[rb * SK + kk];
                bl[1] = *(const uint32_t*)&sVl[rb * SK + kk + 8];
                mma16816(co[dt], ph, bl);
            }
        }
    }

    // ---- epilogue: normalize, write bf16 hi/lo ----
    const float inv0 = 1.f / l0, inv1 = 1.f / l1;
    const size_t row0 = (size_t)(b * SEQ + q0 + wr + lr) * EMB + h * HD;
    const size_t row1 = row0 + (size_t)8 * EMB;
#pragma unroll
    for (int dt = 0; dt < 8; dt++) {
        const int col = dt * 8 + lc;
        float v00 = co[dt][0] * inv0, v01 = co[dt][1] * inv0;
        float v10 = co[dt][2] * inv1, v11 = co[dt][3] * inv1;
        uint32_t h0 = packbf(v00, v01);
        uint32_t h1 = packbf(v10, v11);
        uint32_t lo0 = packbf(v00 - __uint_as_float(h0 << 16),
                              v01 - __uint_as_float(h0 & 0xffff0000u));
        uint32_t lo1 = packbf(v10 - __uint_as_float(h1 << 16),
                              v11 - __uint_as_float(h1 & 0xffff0000u));
        *(uint32_t*)&Oh[row0 + col] = h0;
        *(uint32_t*)&Ol[row0 + col] = lo0;
        *(uint32_t*)&Oh[row1 + col] = h1;
        *(uint32_t*)&Ol[row1 + col] = lo1;
    }
}

// ---------------- LayerNorm ----------------
__global__ __launch_bounds__(256)
void layernorm_kernel(const float* __restrict__ X, const float* __restrict__ gamma,
                      const float* __restrict__ beta, float* __restrict__ out)
{
    __shared__ float ssum[256];
    __shared__ float ssq[256];
    const int row = blockIdx.x;
    const int t = threadIdx.x;
    const float* x = X + (size_t)row * EMB;

    float4 v = *(const float4*)&x[t * 4];
    ssum[t] = v.x + v.y + v.z + v.w;
    ssq[t] = v.x * v.x + v.y * v.y + v.z * v.z + v.w * v.w;
    __syncthreads();
#pragma unroll
    for (int off = 128; off > 0; off >>= 1) {
        if (t < off) {
            ssum[t] += ssum[t + off];
            ssq[t] += ssq[t + off];
        }
        __syncthreads();
    }
    const float mu = ssum[0] * (1.f / EMB);
    const float var = ssq[0] * (1.f / EMB) - mu * mu;
    const float rs = rsqrtf(var + 1e-5f);

    float4 g = *(const float4*)&gamma[t * 4];
    float4 be = *(const float4*)&beta[t * 4];
    float4 o;
    o.x = (v.x - mu) * rs * g.x + be.x;
    o.y = (v.y - mu) * rs * g.y + be.y;
    o.z = (v.z - mu) * rs * g.z + be.z;
    o.w = (v.w - mu) * rs * g.w + be.w;
    *(float4*)&out[(size_t)row * EMB + t * 4] = o;
}

// ---------------- launch ----------------
extern "C" void kernel_launch(void* const* d_in, const int* in_sizes, int n_in,
                              void* d_out, int out_size)
{
    const float* query = (const float*)d_in[0];
    const float* key   = (const float*)d_in[1];
    const float* value = (const float*)d_in[2];
    const float* Wq    = (const float*)d_in[3];
    const float* bq    = (const float*)d_in[4];
    const float* Wk    = (const float*)d_in[5];
    const float* bk    = (const float*)d_in[6];
    const float* Wv    = (const float*)d_in[7];
    const float* bv    = (const float*)d_in[8];
    const float* Wo    = (const float*)d_in[9];
    const float* bo    = (const float*)d_in[10];
    const float* ln_g  = (const float*)d_in[11];
    const float* ln_b  = (const float*)d_in[12];
    float* out = (float*)d_out;

    float *Qf, *Kf, *Vf, *TMPp;
    cudaGetSymbolAddress((void**)&Qf, g_Q);
    cudaGetSymbolAddress((void**)&Kf, g_K);
    cudaGetSymbolAddress((void**)&Vf, g_V);
    cudaGetSymbolAddress((void**)&TMPp, g_TMP);
    // alias fp32 scratch as bf16 hi/lo pairs for projected Q/K/V
    __nv_bfloat16 *Qph = (__nv_bfloat16*)Qf, *Qpl = Qph + NELEM;
    __nv_bfloat16 *Kph = (__nv_bfloat16*)Kf, *Kpl = Kph + NELEM;
    __nv_bfloat16 *Vph = (__nv_bfloat16*)Vf, *Vpl = Vph + NELEM;

    __nv_bfloat16 *qh, *ql, *kh, *kl, *vh, *vl, *oh, *ol;
    __nv_bfloat16 *wqh, *wql, *wkh, *wkl, *wvh, *wvl, *woh, *wol;
    cudaGetSymbolAddress((void**)&qh, g_qh);  cudaGetSymbolAddress((void**)&ql, g_ql);
    cudaGetSymbolAddress((void**)&kh, g_kh);  cudaGetSymbolAddress((void**)&kl, g_kl);
    cudaGetSymbolAddress((void**)&vh, g_vh);  cudaGetSymbolAddress((void**)&vl, g_vl);
    cudaGetSymbolAddress((void**)&oh, g_oh);  cudaGetSymbolAddress((void**)&ol, g_ol);
    cudaGetSymbolAddress((void**)&wqh, g_wqh); cudaGetSymbolAddress((void**)&wql, g_wql);
    cudaGetSymbolAddress((void**)&wkh, g_wkh); cudaGetSymbolAddress((void**)&wkl, g_wkl);
    cudaGetSymbolAddress((void**)&wvh, g_wvh); cudaGetSymbolAddress((void**)&wvl, g_wvl);
    cudaGetSymbolAddress((void**)&woh, g_woh); cudaGetSymbolAddress((void**)&wol, g_wol);

    // 1. split inputs to bf16 hi/lo
    const int split_grid = (int)(NELEM / (256 * 4));  // 4096
    fsplit<<<split_grid, 256>>>(query, qh, ql);
    fsplit<<<split_grid, 256>>>(key,   kh, kl);
    fsplit<<<split_grid, 256>>>(value, vh, vl);

    // 2. transpose + split weights
    dim3 wgrid(EMB / 32, EMB / 32);
    dim3 wblk(32, 8);
    wsplitT<<<wgrid, wblk>>>(Wq, wqh, wql);
    wsplitT<<<wgrid, wblk>>>(Wk, wkh, wkl);
    wsplitT<<<wgrid, wblk>>>(Wv, wvh, wvl);
    wsplitT<<<wgrid, wblk>>>(Wo, woh, wol);

    // 3. projections -> bf16 hi/lo directly (Q pre-scaled by 1/sqrt(HD)=0.125)
    dim3 ggrid(EMB / 128, MROWS / 128);
    gemm_mma<2><<<ggrid, 256>>>(qh, ql, wqh, wql, bq, nullptr, nullptr, Qph, Qpl, 0.125f);
    gemm_mma<2><<<ggrid, 256>>>(kh, kl, wkh, wkl, bk, nullptr, nullptr, Kph, Kpl, 1.0f);
    gemm_mma<2><<<ggrid, 256>>>(vh, vl, wvh, wvl, bv, nullptr, nullptr, Vph, Vpl, 1.0f);

    // 4. attention (tensor-core FA2) -> bf16 hi/lo
    dim3 attn_grid(SEQ / 128, NH, BATCH);   // (16, 16, 2)
    attn_mma<<<attn_grid, 256>>>(Qph, Qpl, Kph, Kpl, Vph, Vpl, oh, ol);

    // 5. output projection + residual (fp32 out)
    gemm_mma<1><<<ggrid, 256>>>(oh, ol, woh, wol, bo, query, TMPp, nullptr, nullptr, 1.0f);

    // 6. layernorm
    layernorm_kernel<<<MROWS, 256>>>(TMPp, ln_g, ln_b, out);
}

// round 8
// speedup vs baseline: 2.3657x; 1.3807x over previous
#include <cuda_runtime.h>
#include <cuda_bf16.h>
#include <math.h>
#include <stdint.h>

#define BATCH 2
#define SEQ 2048
#define EMB 1024
#define NH 16
#define HD 64
#define MROWS (BATCH * SEQ)   // 4096
#define NELEM ((size_t)MROWS * EMB)

// ---------------- device scratch (no allocations allowed) ----------------
__device__ float g_Q[NELEM];
__device__ float g_K[NELEM];
__device__ float g_V[NELEM];
__device__ float g_TMP[NELEM];

__device__ __nv_bfloat16 g_qh[NELEM], g_ql[NELEM];
__device__ __nv_bfloat16 g_kh[NELEM], g_kl[NELEM];
__device__ __nv_bfloat16 g_vh[NELEM], g_vl[NELEM];
__device__ __nv_bfloat16 g_oh[NELEM], g_ol[NELEM];
__device__ __nv_bfloat16 g_wqh[EMB*EMB], g_wql[EMB*EMB];
__device__ __nv_bfloat16 g_wkh[EMB*EMB], g_wkl[EMB*EMB];
__device__ __nv_bfloat16 g_wvh[EMB*EMB], g_wvl[EMB*EMB];
__device__ __nv_bfloat16 g_woh[EMB*EMB], g_wol[EMB*EMB];

// ---------------- helpers ----------------
__device__ __forceinline__ uint32_t s2u(const void* p) {
    uint32_t a;
    asm("{ .reg .u64 t; cvta.to.shared.u64 t, %1; cvt.u32.u64 %0, t; }" : "=r"(a) : "l"(p));
    return a;
}

__device__ __forceinline__ void mma16816(float* c, const uint32_t* a, uint32_t b0, uint32_t b1) {
    asm volatile(
        "mma.sync.aligned.m16n8k16.row.col.f32.bf16.bf16.f32 "
        "{%0,%1,%2,%3}, {%4,%5,%6,%7}, {%8,%9}, {%0,%1,%2,%3};"
        : "+f"(c[0]), "+f"(c[1]), "+f"(c[2]), "+f"(c[3])
        : "r"(a[0]), "r"(a[1]), "r"(a[2]), "r"(a[3]), "r"(b0), "r"(b1));
}

__device__ __forceinline__ uint32_t packbf(float x, float y) {
    uint32_t r;
    asm("cvt.rn.bf16x2.f32 %0, %1, %2;" : "=r"(r) : "f"(y), "f"(x));
    return r;
}

#define CPA(sm, gm) asm volatile("cp.async.cg.shared.global [%0], [%1], 16;" :: "r"(sm), "l"(gm))
#define CPC() asm volatile("cp.async.commit_group;" ::: "memory")
#define CPW(n) asm volatile("cp.async.wait_group %0;" :: "n"(n) : "memory")

#define LDMX4(R0,R1,R2,R3,A) \
    asm volatile("ldmatrix.sync.aligned.m8n8.x4.shared.b16 {%0,%1,%2,%3}, [%4];" \
                 : "=r"(R0), "=r"(R1), "=r"(R2), "=r"(R3) : "r"(A))
#define LDMX4T(R0,R1,R2,R3,A) \
    asm volatile("ldmatrix.sync.aligned.m8n8.x4.trans.shared.b16 {%0,%1,%2,%3}, [%4];" \
                 : "=r"(R0), "=r"(R1), "=r"(R2), "=r"(R3) : "r"(A))

// ---------------- fp32 -> bf16 hi/lo split ----------------
__global__ __launch_bounds__(256)
void fsplit(const float* __restrict__ x, __nv_bfloat16* __restrict__ hi,
            __nv_bfloat16* __restrict__ lo)
{
    size_t i = ((size_t)blockIdx.x * 256 + threadIdx.x) * 4;
    float4 v = *(const float4*)(x + i);
    float vv[4] = {v.x, v.y, v.z, v.w};
    uint32_t ph[2], pl[2];
#pragma unroll
    for (int p = 0; p < 2; p++) {
        uint32_t hp = packbf(vv[2*p], vv[2*p+1]);
        float h0 = __uint_as_float(hp << 16);
        float h1 = __uint_as_float(hp & 0xffff0000u);
        ph[p] = hp;
        pl[p] = packbf(vv[2*p] - h0, vv[2*p+1] - h1);
    }
    *(uint2*)(hi + i) = make_uint2(ph[0], ph[1]);
    *(uint2*)(lo + i) = make_uint2(pl[0], pl[1]);
}

// ---------------- W[K,N] -> Wt[N,K] transpose + hi/lo split ----------------
__global__ __launch_bounds__(256)
void wsplitT(const float* __restrict__ W, __nv_bfloat16* __restrict__ th,
             __nv_bfloat16* __restrict__ tl)
{
    __shared__ float tile[32][33];
    const int n0 = blockIdx.x * 32, k0 = blockIdx.y * 32;
    const int tx = threadIdx.x, ty0 = threadIdx.y;  // (32, 8)
#pragma unroll
    for (int i = 0; i < 4; i++) {
        int ty = ty0 + i * 8;
        tile[ty][tx] = W[(size_t)(k0 + ty) * EMB + n0 + tx];
    }
    __syncthreads();
#pragma unroll
    for (int i = 0; i < 4; i++) {
        int ty = ty0 + i * 8;
        float x = tile[tx][ty];
        __nv_bfloat16 h = __float2bfloat16(x);
        __nv_bfloat16 l = __float2bfloat16(x - __bfloat162float(h));
        th[(size_t)(n0 + ty) * EMB + k0 + tx] = h;
        tl[(size_t)(n0 + ty) * EMB + k0 + tx] = l;
    }
}

// ---------------- mma.sync bf16 split GEMM (cp.async pipelined) ----------------
// MODE 1: fp32 out + bias + residual.  MODE 2: bf16 hi/lo out, (acc+bias)*scale.
#define KC 32
#define SSTR 40
#define GTILEB (128 * SSTR * 2)          // 10240 B per tile
#define GEMM_SMEM (2 * 4 * GTILEB)       // 81920 B

template <int MODE>
__global__ __launch_bounds__(256)
void gemm_mma(const __nv_bfloat16* __restrict__ Ah, const __nv_bfloat16* __restrict__ Al,
              const __nv_bfloat16* __restrict__ Bh, const __nv_bfloat16* __restrict__ Bl,
              const float* __restrict__ bias, const float* __restrict__ res,
              float* __restrict__ Cf, __nv_bfloat16* __restrict__ Ch,
              __nv_bfloat16* __restrict__ Cl, float scale)
{
    extern __shared__ __nv_bfloat16 gsm[];
    const uint32_t smu = s2u(gsm);

    const int t = threadIdx.x;
    const int wid = t >> 5, lane = t & 31;
    const int wm = (wid >> 2) * 64;
    const int wn = (wid & 3) * 32;
    const int lr = lane >> 2;
    const int lc = (lane & 3) * 2;
    const int g = lane >> 3, rowin = lane & 7;
    const int m0 = blockIdx.y * 128;
    const int n0 = blockIdx.x * 128;

    float acc[4][4][4];
#pragma unroll
    for (int mi = 0; mi < 4; mi++)
#pragma unroll
        for (int ni = 0; ni < 4; ni++)
#pragma unroll
            for (int r = 0; r < 4; r++) acc[mi][ni][r] = 0.f;

    auto stage_u = [&](int s, int w) -> uint32_t {
        return smu + (uint32_t)(s * 4 + w) * GTILEB;
    };
    auto load_stage = [&](int s, int k0) {
        uint32_t au = stage_u(s, 0), alu = stage_u(s, 1);
        uint32_t bu = stage_u(s, 2), blu = stage_u(s, 3);
#pragma unroll
        for (int u = 0; u < 2; u++) {
            int idx = t + u * 256;
            int r = idx >> 2;
            int c8 = (idx & 3) * 8;
            uint32_t off = (uint32_t)(r * SSTR + c8) * 2;
            size_t ga = (size_t)(m0 + r) * EMB + k0 + c8;
            size_t gb = (size_t)(n0 + r) * EMB + k0 + c8;
            CPA(au + off, Ah + ga);
            CPA(alu + off, Al + ga);
            CPA(bu + off, Bh + gb);
            CPA(blu + off, Bl + gb);
        }
        CPC();
    };

    load_stage(0, 0);
    const int NK = EMB / KC;   // 32
    for (int it = 0; it < NK; it++) {
        const int s = it & 1;
        if (it + 1 < NK) { load_stage(s ^ 1, (it + 1) * KC); CPW(1); }
        else             { CPW(0); }
        __syncthreads();

        const uint32_t au = stage_u(s, 0), alu = stage_u(s, 1);
        const uint32_t bu = stage_u(s, 2), blu = stage_u(s, 3);
#pragma unroll
        for (int ks = 0; ks < 2; ks++) {
            const int kk = ks * 16;
            uint32_t ah[4][4], al[4][4];
#pragma unroll
            for (int mi = 0; mi < 4; mi++) {
                uint32_t ro = (uint32_t)((wm + mi * 16 + (g & 1) * 8 + rowin) * SSTR
                                         + kk + (g >> 1) * 8) * 2;
                LDMX4(ah[mi][0], ah[mi][1], ah[mi][2], ah[mi][3], au + ro);
                LDMX4(al[mi][0], al[mi][1], al[mi][2], al[mi][3], alu + ro);
            }
#pragma unroll
            for (int p = 0; p < 2; p++) {
                uint32_t ro = (uint32_t)((wn + p * 16 + (g >> 1) * 8 + rowin) * SSTR
                                         + kk + (g & 1) * 8) * 2;
                uint32_t b0, b1, b2, b3, c0, c1, c2, c3;
                LDMX4(b0, b1, b2, b3, bu + ro);
                LDMX4(c0, c1, c2, c3, blu + ro);
#pragma unroll
                for (int mi = 0; mi < 4; mi++) {
                    mma16816(acc[mi][2*p],   ah[mi], b0, b1);
                    mma16816(acc[mi][2*p+1], ah[mi], b2, b3);
                    mma16816(acc[mi][2*p],   ah[mi], c0, c1);
                    mma16816(acc[mi][2*p+1], ah[mi], c2, c3);
                    mma16816(acc[mi][2*p],   al[mi], b0, b1);
                    mma16816(acc[mi][2*p+1], al[mi], b2, b3);
                }
            }
        }
        __syncthreads();
    }

#pragma unroll
    for (int mi = 0; mi < 4; mi++) {
        const int row0 = m0 + wm + mi * 16 + lr;
        const int row1 = row0 + 8;
#pragma unroll
        for (int ni = 0; ni < 4; ni++) {
            const int col = n0 + wn + ni * 8 + lc;
            float2 bs = *(const float2*)&bias[col];
            if (MODE == 2) {
                float v00 = (acc[mi][ni][0] + bs.x) * scale;
                float v01 = (acc[mi][ni][1] + bs.y) * scale;
                float v10 = (acc[mi][ni][2] + bs.x) * scale;
                float v11 = (acc[mi][ni][3] + bs.y) * scale;
                uint32_t h0 = packbf(v00, v01);
                uint32_t h1 = packbf(v10, v11);
                uint32_t l0 = packbf(v00 - __uint_as_float(h0 << 16),
                                     v01 - __uint_as_float(h0 & 0xffff0000u));
                uint32_t l1 = packbf(v10 - __uint_as_float(h1 << 16),
                                     v11 - __uint_as_float(h1 & 0xffff0000u));
                *(uint32_t*)&Ch[(size_t)row0 * EMB + col] = h0;
                *(uint32_t*)&Cl[(size_t)row0 * EMB + col] = l0;
                *(uint32_t*)&Ch[(size_t)row1 * EMB + col] = h1;
                *(uint32_t*)&Cl[(size_t)row1 * EMB + col] = l1;
            } else {
                float2 o0, o1;
                o0.x = acc[mi][ni][0] + bs.x;
                o0.y = acc[mi][ni][1] + bs.y;
                o1.x = acc[mi][ni][2] + bs.x;
                o1.y = acc[mi][ni][3] + bs.y;
                if (MODE == 1) {
                    float2 r0 = *(const float2*)&res[(size_t)row0 * EMB + col];
                    float2 r1 = *(const float2*)&res[(size_t)row1 * EMB + col];
                    o0.x += r0.x; o0.y += r0.y;
                    o1.x += r1.x; o1.y += r1.y;
                }
                *(float2*)&Cf[(size_t)row0 * EMB + col] = o0;
                *(float2*)&Cf[(size_t)row1 * EMB + col] = o1;
            }
        }
    }
}

// ---------------- attention: FA2-style, pipelined, ldmatrix ----------------
// CTA: 128 q-rows, 8 warps x 16 rows. KV blocks of 64. Q pre-scaled by 1/8.
// K and V both stored NATURAL [j][d]; V^T fragments come from ldmatrix.trans.
#define SK 72
#define ATILEB (64 * SK * 2)             // 9216 B
#define ATTN_SMEM (2 * 4 * ATILEB)       // 73728 B

__global__ __launch_bounds__(256)
void attn_mma(const __nv_bfloat16* __restrict__ Qh, const __nv_bfloat16* __restrict__ Ql,
              const __nv_bfloat16* __restrict__ Kh, const __nv_bfloat16* __restrict__ Kl,
              const __nv_bfloat16* __restrict__ Vh, const __nv_bfloat16* __restrict__ Vl,
              __nv_bfloat16* __restrict__ Oh, __nv_bfloat16* __restrict__ Ol)
{
    extern __shared__ __nv_bfloat16 smb[];
    const uint32_t smu = s2u(smb);

    const int t = threadIdx.x;
    const int wid = t >> 5, lane = t & 31;
    const int lr = lane >> 2;
    const int lc = (lane & 3) * 2;
    const int g = lane >> 3, rowin = lane & 7;
    const int q0 = blockIdx.x * 128;
    const int h = blockIdx.y;
    const int b = blockIdx.z;
    const int wr = wid * 16;

    // ---- load Q fragments once (pre-scaled by 1/8 in projection) ----
    uint32_t qah[4][4], qal[4][4];
    {
        const size_t base0 = (size_t)(b * SEQ + q0 + wr + lr) * EMB + h * HD;
        const size_t base1 = base0 + (size_t)8 * EMB;
#pragma unroll
        for (int ks = 0; ks < 4; ks++) {
            const int c0 = ks * 16 + lc;
            qah[ks][0] = *(const uint32_t*)&Qh[base0 + c0];
            qah[ks][1] = *(const uint32_t*)&Qh[base1 + c0];
            qah[ks][2] = *(const uint32_t*)&Qh[base0 + c0 + 8];
            qah[ks][3] = *(const uint32_t*)&Qh[base1 + c0 + 8];
            qal[ks][0] = *(const uint32_t*)&Ql[base0 + c0];
            qal[ks][1] = *(const uint32_t*)&Ql[base1 + c0];
            qal[ks][2] = *(const uint32_t*)&Ql[base0 + c0 + 8];
            qal[ks][3] = *(const uint32_t*)&Ql[base1 + c0 + 8];
        }
    }

    float m0 = -1e30f, m1 = -1e30f, l0 = 0.f, l1 = 0.f;
    float co[8][4];
#pragma unroll
    for (int d = 0; d < 8; d++)
#pragma unroll
        for (int r = 0; r < 4; r++) co[d][r] = 0.f;

    auto stage_u = [&](int s, int w) -> uint32_t {
        return smu + (uint32_t)(s * 4 + w) * ATILEB;
    };
    auto load_stage = [&](int s, int kv0) {
        uint32_t ku = stage_u(s, 0), klu = stage_u(s, 1);
        uint32_t vu = stage_u(s, 2), vlu = stage_u(s, 3);
#pragma unroll
        for (int u = 0; u < 2; u++) {
            int idx = t + u * 256;
            int j = idx >> 3;
            int d0 = (idx & 7) * 8;
            size_t gg = (size_t)(b * SEQ + kv0 + j) * EMB + h * HD + d0;
            uint32_t off = (uint32_t)(j * SK + d0) * 2;
            CPA(ku + off, Kh + gg);
            CPA(klu + off, Kl + gg);
            CPA(vu + off, Vh + gg);
            CPA(vlu + off, Vl + gg);
        }
        CPC();
    };

    load_stage(0, 0);
    const int NB = SEQ / 64;   // 32
    for (int it = 0; it < NB; it++) {
        const int s = it & 1;
        if (it + 1 < NB) { load_stage(s ^ 1, (it + 1) * 64); CPW(1); }
        else             { CPW(0); }
        __syncthreads();

        const uint32_t ku = stage_u(s, 0), klu = stage_u(s, 1);
        const uint32_t vu = stage_u(s, 2), vlu = stage_u(s, 3);

        // ---- S = Qs @ K^T (3-pass split) ----
        float cs[8][4];
#pragma unroll
        for (int n = 0; n < 8; n++)
#pragma unroll
            for (int r = 0; r < 4; r++) cs[n][r] = 0.f;

#pragma unroll
        for (int ks = 0; ks < 4; ks++) {
            const int kk = ks * 16;
#pragma unroll
            for (int p = 0; p < 4; p++) {
                uint32_t ro = (uint32_t)((p * 16 + (g >> 1) * 8 + rowin) * SK
                                         + kk + (g & 1) * 8) * 2;
                uint32_t b0, b1, b2, b3, c0, c1, c2, c3;
                LDMX4(b0, b1, b2, b3, ku + ro);
                LDMX4(c0, c1, c2, c3, klu + ro);
                mma16816(cs[2*p],   qah[ks], b0, b1);
                mma16816(cs[2*p+1], qah[ks], b2, b3);
                mma16816(cs[2*p],   qah[ks], c0, c1);
                mma16816(cs[2*p+1], qah[ks], c2, c3);
                mma16816(cs[2*p],   qal[ks], b0, b1);
                mma16816(cs[2*p+1], qal[ks], b2, b3);
            }
        }

        // ---- online softmax ----
        float rm0 = cs[0][0], rm1 = cs[0][2];
#pragma unroll
        for (int n = 0; n < 8; n++) {
            rm0 = fmaxf(rm0, fmaxf(cs[n][0], cs[n][1]));
            rm1 = fmaxf(rm1, fmaxf(cs[n][2], cs[n][3]));
        }
        rm0 = fmaxf(rm0, __shfl_xor_sync(0xffffffffu, rm0, 1));
        rm0 = fmaxf(rm0, __shfl_xor_sync(0xffffffffu, rm0, 2));
        rm1 = fmaxf(rm1, __shfl_xor_sync(0xffffffffu, rm1, 1));
        rm1 = fmaxf(rm1, __shfl_xor_sync(0xffffffffu, rm1, 2));
        float nm0 = fmaxf(m0, rm0), nm1 = fmaxf(m1, rm1);
        float al0 = __expf(m0 - nm0), al1 = __expf(m1 - nm1);
        float sum0 = 0.f, sum1 = 0.f;
#pragma unroll
        for (int n = 0; n < 8; n++) {
            cs[n][0] = __expf(cs[n][0] - nm0);
            cs[n][1] = __expf(cs[n][1] - nm0);
            cs[n][2] = __expf(cs[n][2] - nm1);
            cs[n][3] = __expf(cs[n][3] - nm1);
            sum0 += cs[n][0] + cs[n][1];
            sum1 += cs[n][2] + cs[n][3];
        }
        sum0 += __shfl_xor_sync(0xffffffffu, sum0, 1);
        sum0 += __shfl_xor_sync(0xffffffffu, sum0, 2);
        sum1 += __shfl_xor_sync(0xffffffffu, sum1, 1);
        sum1 += __shfl_xor_sync(0xffffffffu, sum1, 2);
        l0 = l0 * al0 + sum0;  m0 = nm0;
        l1 = l1 * al1 + sum1;  m1 = nm1;
#pragma unroll
        for (int d = 0; d < 8; d++) {
            co[d][0] *= al0; co[d][1] *= al0;
            co[d][2] *= al1; co[d][3] *= al1;
        }

        // ---- O += P @ V (3-pass split; V^T fragments via ldmatrix.trans) ----
#pragma unroll
        for (int ks = 0; ks < 4; ks++) {
            uint32_t ph[4], pl[4];
#pragma unroll
            for (int half = 0; half < 2; half++) {
                const float* c0p = cs[2 * ks + half];
                uint32_t hA = packbf(c0p[0], c0p[1]);
                uint32_t hB = packbf(c0p[2], c0p[3]);
                ph[2 * half    ] = hA;
                ph[2 * half + 1] = hB;
                pl[2 * half    ] = packbf(c0p[0] - __uint_as_float(hA << 16),
                                          c0p[1] - __uint_as_float(hA & 0xffff0000u));
                pl[2 * half + 1] = packbf(c0p[2] - __uint_as_float(hB << 16),
                                          c0p[3] - __uint_as_float(hB & 0xffff0000u));
            }
            const int kk = ks * 16;
#pragma unroll
            for (int p = 0; p < 4; p++) {
                uint32_t ro = (uint32_t)((kk + (g & 1) * 8 + rowin) * SK
                                         + p * 16 + (g >> 1) * 8) * 2;
                uint32_t b0, b1, b2, b3, c0, c1, c2, c3;
                LDMX4T(b0, b1, b2, b3, vu + ro);
                LDMX4T(c0, c1, c2, c3, vlu + ro);
                mma16816(co[2*p],   ph, b0, b1);
                mma16816(co[2*p+1], ph, b2, b3);
                mma16816(co[2*p],   pl, b0, b1);
                mma16816(co[2*p+1], pl, b2, b3);
                mma16816(co[2*p],   ph, c0, c1);
                mma16816(co[2*p+1], ph, c2, c3);
            }
        }
        __syncthreads();
    }

    // ---- epilogue: normalize, write bf16 hi/lo ----
    const float inv0 = 1.f / l0, inv1 = 1.f / l1;
    const size_t row0 = (size_t)(b * SEQ + q0 + wr + lr) * EMB + h * HD;
    const size_t row1 = row0 + (size_t)8 * EMB;
#pragma unroll
    for (int dt = 0; dt < 8; dt++) {
        const int col = dt * 8 + lc;
        float v00 = co[dt][0] * inv0, v01 = co[dt][1] * inv0;
        float v10 = co[dt][2] * inv1, v11 = co[dt][3] * inv1;
        uint32_t h0 = packbf(v00, v01);
        uint32_t h1 = packbf(v10, v11);
        uint32_t lo0 = packbf(v00 - __uint_as_float(h0 << 16),
                              v01 - __uint_as_float(h0 & 0xffff0000u));
        uint32_t lo1 = packbf(v10 - __uint_as_float(h1 << 16),
                              v11 - __uint_as_float(h1 & 0xffff0000u));
        *(uint32_t*)&Oh[row0 + col] = h0;
        *(uint32_t*)&Ol[row0 + col] = lo0;
        *(uint32_t*)&Oh[row1 + col] = h1;
        *(uint32_t*)&Ol[row1 + col] = lo1;
    }
}

// ---------------- LayerNorm ----------------
__global__ __launch_bounds__(256)
void layernorm_kernel(const float* __restrict__ X, const float* __restrict__ gamma,
                      const float* __restrict__ beta, float* __restrict__ out)
{
    __shared__ float ssum[256];
    __shared__ float ssq[256];
    const int row = blockIdx.x;
    const int t = threadIdx.x;
    const float* x = X + (size_t)row * EMB;

    float4 v = *(const float4*)&x[t * 4];
    ssum[t] = v.x + v.y + v.z + v.w;
    ssq[t] = v.x * v.x + v.y * v.y + v.z * v.z + v.w * v.w;
    __syncthreads();
#pragma unroll
    for (int off = 128; off > 0; off >>= 1) {
        if (t < off) {
            ssum[t] += ssum[t + off];
            ssq[t] += ssq[t + off];
        }
        __syncthreads();
    }
    const float mu = ssum[0] * (1.f / EMB);
    const float var = ssq[0] * (1.f / EMB) - mu * mu;
    const float rs = rsqrtf(var + 1e-5f);

    float4 gm = *(const float4*)&gamma[t * 4];
    float4 be = *(const float4*)&beta[t * 4];
    float4 o;
    o.x = (v.x - mu) * rs * gm.x + be.x;
    o.y = (v.y - mu) * rs * gm.y + be.y;
    o.z = (v.z - mu) * rs * gm.z + be.z;
    o.w = (v.w - mu) * rs * gm.w + be.w;
    *(float4*)&out[(size_t)row * EMB + t * 4] = o;
}

// ---------------- launch ----------------
extern "C" void kernel_launch(void* const* d_in, const int* in_sizes, int n_in,
                              void* d_out, int out_size)
{
    const float* query = (const float*)d_in[0];
    const float* key   = (const float*)d_in[1];
    const float* value = (const float*)d_in[2];
    const float* Wq    = (const float*)d_in[3];
    const float* bq    = (const float*)d_in[4];
    const float* Wk    = (const float*)d_in[5];
    const float* bk    = (const float*)d_in[6];
    const float* Wv    = (const float*)d_in[7];
    const float* bv    = (const float*)d_in[8];
    const float* Wo    = (const float*)d_in[9];
    const float* bo    = (const float*)d_in[10];
    const float* ln_g  = (const float*)d_in[11];
    const float* ln_b  = (const float*)d_in[12];
    float* out = (float*)d_out;

    float *Qf, *Kf, *Vf, *TMPp;
    cudaGetSymbolAddress((void**)&Qf, g_Q);
    cudaGetSymbolAddress((void**)&Kf, g_K);
    cudaGetSymbolAddress((void**)&Vf, g_V);
    cudaGetSymbolAddress((void**)&TMPp, g_TMP);
    __nv_bfloat16 *Qph = (__nv_bfloat16*)Qf, *Qpl = Qph + NELEM;
    __nv_bfloat16 *Kph = (__nv_bfloat16*)Kf, *Kpl = Kph + NELEM;
    __nv_bfloat16 *Vph = (__nv_bfloat16*)Vf, *Vpl = Vph + NELEM;

    __nv_bfloat16 *qh, *ql, *kh, *kl, *vh, *vl, *oh, *ol;
    __nv_bfloat16 *wqh, *wql, *wkh, *wkl, *wvh, *wvl, *woh, *wol;
    cudaGetSymbolAddress((void**)&qh, g_qh);  cudaGetSymbolAddress((void**)&ql, g_ql);
    cudaGetSymbolAddress((void**)&kh, g_kh);  cudaGetSymbolAddress((void**)&kl, g_kl);
    cudaGetSymbolAddress((void**)&vh, g_vh);  cudaGetSymbolAddress((void**)&vl, g_vl);
    cudaGetSymbolAddress((void**)&oh, g_oh);  cudaGetSymbolAddress((void**)&ol, g_ol);
    cudaGetSymbolAddress((void**)&wqh, g_wqh); cudaGetSymbolAddress((void**)&wql, g_wql);
    cudaGetSymbolAddress((void**)&wkh, g_wkh); cudaGetSymbolAddress((void**)&wkl, g_wkl);
    cudaGetSymbolAddress((void**)&wvh, g_wvh); cudaGetSymbolAddress((void**)&wvl, g_wvl);
    cudaGetSymbolAddress((void**)&woh, g_woh); cudaGetSymbolAddress((void**)&wol, g_wol);

    static bool attr_set = false;
    if (!attr_set) {
        cudaFuncSetAttribute(gemm_mma<1>, cudaFuncAttributeMaxDynamicSharedMemorySize, GEMM_SMEM);
        cudaFuncSetAttribute(gemm_mma<2>, cudaFuncAttributeMaxDynamicSharedMemorySize, GEMM_SMEM);
        cudaFuncSetAttribute(attn_mma, cudaFuncAttributeMaxDynamicSharedMemorySize, ATTN_SMEM);
        attr_set = true;
    }

    // 1. split inputs to bf16 hi/lo
    const int split_grid = (int)(NELEM / (256 * 4));  // 4096
    fsplit<<<split_grid, 256>>>(query, qh, ql);
    fsplit<<<split_grid, 256>>>(key,   kh, kl);
    fsplit<<<split_grid, 256>>>(value, vh, vl);

    // 2. transpose + split weights
    dim3 wgrid(EMB / 32, EMB / 32);
    dim3 wblk(32, 8);
    wsplitT<<<wgrid, wblk>>>(Wq, wqh, wql);
    wsplitT<<<wgrid, wblk>>>(Wk, wkh, wkl);
    wsplitT<<<wgrid, wblk>>>(Wv, wvh, wvl);
    wsplitT<<<wgrid, wblk>>>(Wo, woh, wol);

    // 3. projections -> bf16 hi/lo (Q pre-scaled by 0.125)
    dim3 ggrid(EMB / 128, MROWS / 128);
    gemm_mma<2><<<ggrid, 256, GEMM_SMEM>>>(qh, ql, wqh, wql, bq, nullptr, nullptr, Qph, Qpl, 0.125f);
    gemm_mma<2><<<ggrid, 256, GEMM_SMEM>>>(kh, kl, wkh, wkl, bk, nullptr, nullptr, Kph, Kpl, 1.0f);
    gemm_mma<2><<<ggrid, 256, GEMM_SMEM>>>(vh, vl, wvh, wvl, bv, nullptr, nullptr, Vph, Vpl, 1.0f);

    // 4. attention
    dim3 attn_grid(SEQ / 128, NH, BATCH);   // (16, 16, 2)
    attn_mma<<<attn_grid, 256, ATTN_SMEM>>>(Qph, Qpl, Kph, Kpl, Vph, Vpl, oh, ol);

    // 5. output projection + residual (fp32 out)
    gemm_mma<1><<<ggrid, 256, GEMM_SMEM>>>(oh, ol, woh, wol, bo, query, TMPp, nullptr, nullptr, 1.0f);

    // 6. layernorm
    layernorm_kernel<<<MROWS, 256>>>(TMPp, ln_g, ln_b, out);
}

// round 9
// speedup vs baseline: 2.3670x; 1.0005x over previous
#include <cuda_runtime.h>
#include <cuda_bf16.h>
#include <math.h>
#include <stdint.h>

#define BATCH 2
#define SEQ 2048
#define EMB 1024
#define NH 16
#define HD 64
#define MROWS (BATCH * SEQ)   // 4096
#define NELEM ((size_t)MROWS * EMB)

// ---------------- device scratch (no allocations allowed) ----------------
__device__ float g_Q[NELEM];
__device__ float g_K[NELEM];
__device__ float g_V[NELEM];
__device__ float g_TMP[NELEM];

__device__ __nv_bfloat16 g_qh[NELEM], g_ql[NELEM];
__device__ __nv_bfloat16 g_kh[NELEM], g_kl[NELEM];
__device__ __nv_bfloat16 g_vh[NELEM], g_vl[NELEM];
__device__ __nv_bfloat16 g_oh[NELEM], g_ol[NELEM];
__device__ __nv_bfloat16 g_wqh[EMB*EMB], g_wql[EMB*EMB];
__device__ __nv_bfloat16 g_wkh[EMB*EMB], g_wkl[EMB*EMB];
__device__ __nv_bfloat16 g_wvh[EMB*EMB], g_wvl[EMB*EMB];
__device__ __nv_bfloat16 g_woh[EMB*EMB], g_wol[EMB*EMB];

// ---------------- helpers ----------------
__device__ __forceinline__ uint32_t s2u(const void* p) {
    uint32_t a;
    asm("{ .reg .u64 t; cvta.to.shared.u64 t, %1; cvt.u32.u64 %0, t; }" : "=r"(a) : "l"(p));
    return a;
}

__device__ __forceinline__ void mma16816(float* c, const uint32_t* a, uint32_t b0, uint32_t b1) {
    asm volatile(
        "mma.sync.aligned.m16n8k16.row.col.f32.bf16.bf16.f32 "
        "{%0,%1,%2,%3}, {%4,%5,%6,%7}, {%8,%9}, {%0,%1,%2,%3};"
        : "+f"(c[0]), "+f"(c[1]), "+f"(c[2]), "+f"(c[3])
        : "r"(a[0]), "r"(a[1]), "r"(a[2]), "r"(a[3]), "r"(b0), "r"(b1));
}

__device__ __forceinline__ uint32_t packbf(float x, float y) {
    uint32_t r;
    asm("cvt.rn.bf16x2.f32 %0, %1, %2;" : "=r"(r) : "f"(y), "f"(x));
    return r;
}

#define CPA(sm, gm) asm volatile("cp.async.cg.shared.global [%0], [%1], 16;" :: "r"(sm), "l"(gm))
#define CPC() asm volatile("cp.async.commit_group;" ::: "memory")
#define CPW(n) asm volatile("cp.async.wait_group %0;" :: "n"(n) : "memory")

#define LDMX4(R0,R1,R2,R3,A) \
    asm volatile("ldmatrix.sync.aligned.m8n8.x4.shared.b16 {%0,%1,%2,%3}, [%4];" \
                 : "=r"(R0), "=r"(R1), "=r"(R2), "=r"(R3) : "r"(A))
#define LDMX4T(R0,R1,R2,R3,A) \
    asm volatile("ldmatrix.sync.aligned.m8n8.x4.trans.shared.b16 {%0,%1,%2,%3}, [%4];" \
                 : "=r"(R0), "=r"(R1), "=r"(R2), "=r"(R3) : "r"(A))

// ---------------- batched fp32 -> bf16 hi/lo split (3 tensors) ----------------
struct Split3Args {
    const float* x[3];
    __nv_bfloat16* hi[3];
    __nv_bfloat16* lo[3];
};

__global__ __launch_bounds__(256)
void fsplit3(Split3Args a)
{
    const int z = blockIdx.y;
    const float* x = a.x[z];
    __nv_bfloat16* hi = a.hi[z];
    __nv_bfloat16* lo = a.lo[z];
    size_t i = ((size_t)blockIdx.x * 256 + threadIdx.x) * 4;
    float4 v = *(const float4*)(x + i);
    float vv[4] = {v.x, v.y, v.z, v.w};
    uint32_t ph[2], pl[2];
#pragma unroll
    for (int p = 0; p < 2; p++) {
        uint32_t hp = packbf(vv[2*p], vv[2*p+1]);
        float h0 = __uint_as_float(hp << 16);
        float h1 = __uint_as_float(hp & 0xffff0000u);
        ph[p] = hp;
        pl[p] = packbf(vv[2*p] - h0, vv[2*p+1] - h1);
    }
    *(uint2*)(hi + i) = make_uint2(ph[0], ph[1]);
    *(uint2*)(lo + i) = make_uint2(pl[0], pl[1]);
}

// ---------------- batched W[K,N] -> Wt[N,K] transpose + hi/lo split (4 weights) ----------------
struct WSplit4Args {
    const float* W[4];
    __nv_bfloat16* th[4];
    __nv_bfloat16* tl[4];
};

__global__ __launch_bounds__(256)
void wsplit4(WSplit4Args a)
{
    __shared__ float tile[32][33];
    const int z = blockIdx.z;
    const float* W = a.W[z];
    __nv_bfloat16* th = a.th[z];
    __nv_bfloat16* tl = a.tl[z];
    const int n0 = blockIdx.x * 32, k0 = blockIdx.y * 32;
    const int tx = threadIdx.x, ty0 = threadIdx.y;  // (32, 8)
#pragma unroll
    for (int i = 0; i < 4; i++) {
        int ty = ty0 + i * 8;
        tile[ty][tx] = W[(size_t)(k0 + ty) * EMB + n0 + tx];
    }
    __syncthreads();
#pragma unroll
    for (int i = 0; i < 4; i++) {
        int ty = ty0 + i * 8;
        float x = tile[tx][ty];
        __nv_bfloat16 h = __float2bfloat16(x);
        __nv_bfloat16 l = __float2bfloat16(x - __bfloat162float(h));
        th[(size_t)(n0 + ty) * EMB + k0 + tx] = h;
        tl[(size_t)(n0 + ty) * EMB + k0 + tx] = l;
    }
}

// ---------------- mma.sync bf16 split GEMM core (cp.async 2-stage) ----------------
// MODE 1: fp32 out + bias + residual.  MODE 2: bf16 hi/lo out, (acc+bias)*scale.
#define KC 32
#define SSTR 40
#define GTILEB (128 * SSTR * 2)          // 10240 B per tile
#define GEMM_SMEM (2 * 4 * GTILEB)       // 81920 B

template <int MODE>
__device__ __forceinline__
void gemm_body(const __nv_bfloat16* __restrict__ Ah, const __nv_bfloat16* __restrict__ Al,
               const __nv_bfloat16* __restrict__ Bh, const __nv_bfloat16* __restrict__ Bl,
               const float* __restrict__ bias, const float* __restrict__ res,
               float* __restrict__ Cf, __nv_bfloat16* __restrict__ Ch,
               __nv_bfloat16* __restrict__ Cl, float scale)
{
    extern __shared__ __nv_bfloat16 gsm[];
    const uint32_t smu = s2u(gsm);

    const int t = threadIdx.x;
    const int wid = t >> 5, lane = t & 31;
    const int wm = (wid >> 2) * 64;
    const int wn = (wid & 3) * 32;
    const int lr = lane >> 2;
    const int lc = (lane & 3) * 2;
    const int g = lane >> 3, rowin = lane & 7;
    const int m0 = blockIdx.y * 128;
    const int n0 = blockIdx.x * 128;

    float acc[4][4][4];
#pragma unroll
    for (int mi = 0; mi < 4; mi++)
#pragma unroll
        for (int ni = 0; ni < 4; ni++)
#pragma unroll
            for (int r = 0; r < 4; r++) acc[mi][ni][r] = 0.f;

    auto stage_u = [&](int s, int w) -> uint32_t {
        return smu + (uint32_t)(s * 4 + w) * GTILEB;
    };
    auto load_stage = [&](int s, int k0) {
        uint32_t au = stage_u(s, 0), alu = stage_u(s, 1);
        uint32_t bu = stage_u(s, 2), blu = stage_u(s, 3);
#pragma unroll
        for (int u = 0; u < 2; u++) {
            int idx = t + u * 256;
            int r = idx >> 2;
            int c8 = (idx & 3) * 8;
            uint32_t off = (uint32_t)(r * SSTR + c8) * 2;
            size_t ga = (size_t)(m0 + r) * EMB + k0 + c8;
            size_t gb = (size_t)(n0 + r) * EMB + k0 + c8;
            CPA(au + off, Ah + ga);
            CPA(alu + off, Al + ga);
            CPA(bu + off, Bh + gb);
            CPA(blu + off, Bl + gb);
        }
        CPC();
    };

    load_stage(0, 0);
    const int NK = EMB / KC;   // 32
    for (int it = 0; it < NK; it++) {
        const int s = it & 1;
        if (it + 1 < NK) { load_stage(s ^ 1, (it + 1) * KC); CPW(1); }
        else             { CPW(0); }
        __syncthreads();

        const uint32_t au = stage_u(s, 0), alu = stage_u(s, 1);
        const uint32_t bu = stage_u(s, 2), blu = stage_u(s, 3);
#pragma unroll
        for (int ks = 0; ks < 2; ks++) {
            const int kk = ks * 16;
            uint32_t ah[4][4], al[4][4];
#pragma unroll
            for (int mi = 0; mi < 4; mi++) {
                uint32_t ro = (uint32_t)((wm + mi * 16 + (g & 1) * 8 + rowin) * SSTR
                                         + kk + (g >> 1) * 8) * 2;
                LDMX4(ah[mi][0], ah[mi][1], ah[mi][2], ah[mi][3], au + ro);
                LDMX4(al[mi][0], al[mi][1], al[mi][2], al[mi][3], alu + ro);
            }
#pragma unroll
            for (int p = 0; p < 2; p++) {
                uint32_t ro = (uint32_t)((wn + p * 16 + (g >> 1) * 8 + rowin) * SSTR
                                         + kk + (g & 1) * 8) * 2;
                uint32_t b0, b1, b2, b3, c0, c1, c2, c3;
                LDMX4(b0, b1, b2, b3, bu + ro);
                LDMX4(c0, c1, c2, c3, blu + ro);
#pragma unroll
                for (int mi = 0; mi < 4; mi++) {
                    mma16816(acc[mi][2*p],   ah[mi], b0, b1);
                    mma16816(acc[mi][2*p+1], ah[mi], b2, b3);
                    mma16816(acc[mi][2*p],   ah[mi], c0, c1);
                    mma16816(acc[mi][2*p+1], ah[mi], c2, c3);
                    mma16816(acc[mi][2*p],   al[mi], b0, b1);
                    mma16816(acc[mi][2*p+1], al[mi], b2, b3);
                }
            }
        }
        __syncthreads();
    }

#pragma unroll
    for (int mi = 0; mi < 4; mi++) {
        const int row0 = m0 + wm + mi * 16 + lr;
        const int row1 = row0 + 8;
#pragma unroll
        for (int ni = 0; ni < 4; ni++) {
            const int col = n0 + wn + ni * 8 + lc;
            float2 bs = *(const float2*)&bias[col];
            if (MODE == 2) {
                float v00 = (acc[mi][ni][0] + bs.x) * scale;
                float v01 = (acc[mi][ni][1] + bs.y) * scale;
                float v10 = (acc[mi][ni][2] + bs.x) * scale;
                float v11 = (acc[mi][ni][3] + bs.y) * scale;
                uint32_t h0 = packbf(v00, v01);
                uint32_t h1 = packbf(v10, v11);
                uint32_t l0 = packbf(v00 - __uint_as_float(h0 << 16),
                                     v01 - __uint_as_float(h0 & 0xffff0000u));
                uint32_t l1 = packbf(v10 - __uint_as_float(h1 << 16),
                                     v11 - __uint_as_float(h1 & 0xffff0000u));
                *(uint32_t*)&Ch[(size_t)row0 * EMB + col] = h0;
                *(uint32_t*)&Cl[(size_t)row0 * EMB + col] = l0;
                *(uint32_t*)&Ch[(size_t)row1 * EMB + col] = h1;
                *(uint32_t*)&Cl[(size_t)row1 * EMB + col] = l1;
            } else {
                float2 o0, o1;
                o0.x = acc[mi][ni][0] + bs.x;
                o0.y = acc[mi][ni][1] + bs.y;
                o1.x = acc[mi][ni][2] + bs.x;
                o1.y = acc[mi][ni][3] + bs.y;
                if (MODE == 1) {
                    float2 r0 = *(const float2*)&res[(size_t)row0 * EMB + col];
                    float2 r1 = *(const float2*)&res[(size_t)row1 * EMB + col];
                    o0.x += r0.x; o0.y += r0.y;
                    o1.x += r1.x; o1.y += r1.y;
                }
                *(float2*)&Cf[(size_t)row0 * EMB + col] = o0;
                *(float2*)&Cf[(size_t)row1 * EMB + col] = o1;
            }
        }
    }
}

// merged Q/K/V projection: gridDim.z = 3 selects tensor
struct GemmQKVArgs {
    const __nv_bfloat16* Ah[3];
    const __nv_bfloat16* Al[3];
    const __nv_bfloat16* Bh[3];
    const __nv_bfloat16* Bl[3];
    const float* bias[3];
    __nv_bfloat16* Ch[3];
    __nv_bfloat16* Cl[3];
};

__global__ __launch_bounds__(256)
void gemm_qkv(GemmQKVArgs a)
{
    const int z = blockIdx.z;
    gemm_body<2>(a.Ah[z], a.Al[z], a.Bh[z], a.Bl[z], a.bias[z], nullptr,
                 nullptr, a.Ch[z], a.Cl[z], z == 0 ? 0.125f : 1.0f);
}

__global__ __launch_bounds__(256)
void gemm_out(const __nv_bfloat16* __restrict__ Ah, const __nv_bfloat16* __restrict__ Al,
              const __nv_bfloat16* __restrict__ Bh, const __nv_bfloat16* __restrict__ Bl,
              const float* __restrict__ bias, const float* __restrict__ res,
              float* __restrict__ Cf)
{
    gemm_body<1>(Ah, Al, Bh, Bl, bias, res, Cf, nullptr, nullptr, 1.0f);
}

// ---------------- attention: FA2-style, 3-stage cp.async, ldmatrix ----------------
#define SK 72
#define ATILEB (64 * SK * 2)             // 9216 B
#define NSTG 3
#define ATTN_SMEM (NSTG * 4 * ATILEB)    // 110592 B

__global__ __launch_bounds__(256)
void attn_mma(const __nv_bfloat16* __restrict__ Qh, const __nv_bfloat16* __restrict__ Ql,
              const __nv_bfloat16* __restrict__ Kh, const __nv_bfloat16* __restrict__ Kl,
              const __nv_bfloat16* __restrict__ Vh, const __nv_bfloat16* __restrict__ Vl,
              __nv_bfloat16* __restrict__ Oh, __nv_bfloat16* __restrict__ Ol)
{
    extern __shared__ __nv_bfloat16 smb[];
    const uint32_t smu = s2u(smb);

    const int t = threadIdx.x;
    const int wid = t >> 5, lane = t & 31;
    const int lr = lane >> 2;
    const int lc = (lane & 3) * 2;
    const int g = lane >> 3, rowin = lane & 7;
    const int q0 = blockIdx.x * 128;
    const int h = blockIdx.y;
    const int b = blockIdx.z;
    const int wr = wid * 16;

    // ---- load Q fragments once (pre-scaled by 1/8 in projection) ----
    uint32_t qah[4][4], qal[4][4];
    {
        const size_t base0 = (size_t)(b * SEQ + q0 + wr + lr) * EMB + h * HD;
        const size_t base1 = base0 + (size_t)8 * EMB;
#pragma unroll
        for (int ks = 0; ks < 4; ks++) {
            const int c0 = ks * 16 + lc;
            qah[ks][0] = *(const uint32_t*)&Qh[base0 + c0];
            qah[ks][1] = *(const uint32_t*)&Qh[base1 + c0];
            qah[ks][2] = *(const uint32_t*)&Qh[base0 + c0 + 8];
            qah[ks][3] = *(const uint32_t*)&Qh[base1 + c0 + 8];
            qal[ks][0] = *(const uint32_t*)&Ql[base0 + c0];
            qal[ks][1] = *(const uint32_t*)&Ql[base1 + c0];
            qal[ks][2] = *(const uint32_t*)&Ql[base0 + c0 + 8];
            qal[ks][3] = *(const uint32_t*)&Ql[base1 + c0 + 8];
        }
    }

    float m0 = -1e30f, m1 = -1e30f, l0 = 0.f, l1 = 0.f;
    float co[8][4];
#pragma unroll
    for (int d = 0; d < 8; d++)
#pragma unroll
        for (int r = 0; r < 4; r++) co[d][r] = 0.f;

    auto stage_u = [&](int s, int w) -> uint32_t {
        return smu + (uint32_t)(s * 4 + w) * ATILEB;
    };
    auto load_stage = [&](int s, int kv0) {
        uint32_t ku = stage_u(s, 0), klu = stage_u(s, 1);
        uint32_t vu = stage_u(s, 2), vlu = stage_u(s, 3);
#pragma unroll
        for (int u = 0; u < 2; u++) {
            int idx = t + u * 256;
            int j = idx >> 3;
            int d0 = (idx & 7) * 8;
            size_t gg = (size_t)(b * SEQ + kv0 + j) * EMB + h * HD + d0;
            uint32_t off = (uint32_t)(j * SK + d0) * 2;
            CPA(ku + off, Kh + gg);
            CPA(klu + off, Kl + gg);
            CPA(vu + off, Vh + gg);
            CPA(vlu + off, Vl + gg);
        }
        CPC();
    };

    const int NB = SEQ / 64;   // 32
    load_stage(0, 0);
    load_stage(1, 64);
    for (int it = 0; it < NB; it++) {
        const int s = it % NSTG;
        if (it + 2 < NB) { load_stage((it + 2) % NSTG, (it + 2) * 64); CPW(2); }
        else if (it + 1 < NB) { CPW(1); }
        else { CPW(0); }
        __syncthreads();

        const uint32_t ku = stage_u(s, 0), klu = stage_u(s, 1);
        const uint32_t vu = stage_u(s, 2), vlu = stage_u(s, 3);

        // ---- S = Qs @ K^T (3-pass split) ----
        float cs[8][4];
#pragma unroll
        for (int n = 0; n < 8; n++)
#pragma unroll
            for (int r = 0; r < 4; r++) cs[n][r] = 0.f;

#pragma unroll
        for (int ks = 0; ks < 4; ks++) {
            const int kk = ks * 16;
#pragma unroll
            for (int p = 0; p < 4; p++) {
                uint32_t ro = (uint32_t)((p * 16 + (g >> 1) * 8 + rowin) * SK
                                         + kk + (g & 1) * 8) * 2;
                uint32_t b0, b1, b2, b3, c0, c1, c2, c3;
                LDMX4(b0, b1, b2, b3, ku + ro);
                LDMX4(c0, c1, c2, c3, klu + ro);
                mma16816(cs[2*p],   qah[ks], b0, b1);
                mma16816(cs[2*p+1], qah[ks], b2, b3);
                mma16816(cs[2*p],   qah[ks], c0, c1);
                mma16816(cs[2*p+1], qah[ks], c2, c3);
                mma16816(cs[2*p],   qal[ks], b0, b1);
                mma16816(cs[2*p+1], qal[ks], b2, b3);
            }
        }

        // ---- online softmax ----
        float rm0 = cs[0][0], rm1 = cs[0][2];
#pragma unroll
        for (int n = 0; n < 8; n++) {
            rm0 = fmaxf(rm0, fmaxf(cs[n][0], cs[n][1]));
            rm1 = fmaxf(rm1, fmaxf(cs[n][2], cs[n][3]));
        }
        rm0 = fmaxf(rm0, __shfl_xor_sync(0xffffffffu, rm0, 1));
        rm0 = fmaxf(rm0, __shfl_xor_sync(0xffffffffu, rm0, 2));
        rm1 = fmaxf(rm1, __shfl_xor_sync(0xffffffffu, rm1, 1));
        rm1 = fmaxf(rm1, __shfl_xor_sync(0xffffffffu, rm1, 2));
        float nm0 = fmaxf(m0, rm0), nm1 = fmaxf(m1, rm1);
        float al0 = __expf(m0 - nm0), al1 = __expf(m1 - nm1);
        float sum0 = 0.f, sum1 = 0.f;
#pragma unroll
        for (int n = 0; n < 8; n++) {
            cs[n][0] = __expf(cs[n][0] - nm0);
            cs[n][1] = __expf(cs[n][1] - nm0);
            cs[n][2] = __expf(cs[n][2] - nm1);
            cs[n][3] = __expf(cs[n][3] - nm1);
            sum0 += cs[n][0] + cs[n][1];
            sum1 += cs[n][2] + cs[n][3];
        }
        sum0 += __shfl_xor_sync(0xffffffffu, sum0, 1);
        sum0 += __shfl_xor_sync(0xffffffffu, sum0, 2);
        sum1 += __shfl_xor_sync(0xffffffffu, sum1, 1);
        sum1 += __shfl_xor_sync(0xffffffffu, sum1, 2);
        l0 = l0 * al0 + sum0;  m0 = nm0;
        l1 = l1 * al1 + sum1;  m1 = nm1;
#pragma unroll
        for (int d = 0; d < 8; d++) {
            co[d][0] *= al0; co[d][1] *= al0;
            co[d][2] *= al1; co[d][3] *= al1;
        }

        // ---- O += P @ V (3-pass split; V^T via ldmatrix.trans) ----
#pragma unroll
        for (int ks = 0; ks < 4; ks++) {
            uint32_t ph[4], pl[4];
#pragma unroll
            for (int half = 0; half < 2; half++) {
                const float* c0p = cs[2 * ks + half];
                uint32_t hA = packbf(c0p[0], c0p[1]);
                uint32_t hB = packbf(c0p[2], c0p[3]);
                ph[2 * half    ] = hA;
                ph[2 * half + 1] = hB;
                pl[2 * half    ] = packbf(c0p[0] - __uint_as_float(hA << 16),
                                          c0p[1] - __uint_as_float(hA & 0xffff0000u));
                pl[2 * half + 1] = packbf(c0p[2] - __uint_as_float(hB << 16),
                                          c0p[3] - __uint_as_float(hB & 0xffff0000u));
            }
            const int kk = ks * 16;
#pragma unroll
            for (int p = 0; p < 4; p++) {
                uint32_t ro = (uint32_t)((kk + (g & 1) * 8 + rowin) * SK
                                         + p * 16 + (g >> 1) * 8) * 2;
                uint32_t b0, b1, b2, b3, c0, c1, c2, c3;
                LDMX4T(b0, b1, b2, b3, vu + ro);
                LDMX4T(c0, c1, c2, c3, vlu + ro);
                mma16816(co[2*p],   ph, b0, b1);
                mma16816(co[2*p+1], ph, b2, b3);
                mma16816(co[2*p],   pl, b0, b1);
                mma16816(co[2*p+1], pl, b2, b3);
                mma16816(co[2*p],   ph, c0, c1);
                mma16816(co[2*p+1], ph, c2, c3);
            }
        }
        __syncthreads();
    }

    // ---- epilogue: normalize, write bf16 hi/lo ----
    const float inv0 = 1.f / l0, inv1 = 1.f / l1;
    const size_t row0 = (size_t)(b * SEQ + q0 + wr + lr) * EMB + h * HD;
    const size_t row1 = row0 + (size_t)8 * EMB;
#pragma unroll
    for (int dt = 0; dt < 8; dt++) {
        const int col = dt * 8 + lc;
        float v00 = co[dt][0] * inv0, v01 = co[dt][1] * inv0;
        float v10 = co[dt][2] * inv1, v11 = co[dt][3] * inv1;
        uint32_t h0 = packbf(v00, v01);
        uint32_t h1 = packbf(v10, v11);
        uint32_t lo0 = packbf(v00 - __uint_as_float(h0 << 16),
                              v01 - __uint_as_float(h0 & 0xffff0000u));
        uint32_t lo1 = packbf(v10 - __uint_as_float(h1 << 16),
                              v11 - __uint_as_float(h1 & 0xffff0000u));
        *(uint32_t*)&Oh[row0 + col] = h0;
        *(uint32_t*)&Ol[row0 + col] = lo0;
        *(uint32_t*)&Oh[row1 + col] = h1;
        *(uint32_t*)&Ol[row1 + col] = lo1;
    }
}

// ---------------- LayerNorm ----------------
__global__ __launch_bounds__(256)
void layernorm_kernel(const float* __restrict__ X, const float* __restrict__ gamma,
                      const float* __restrict__ beta, float* __restrict__ out)
{
    __shared__ float ssum[256];
    __shared__ float ssq[256];
    const int row = blockIdx.x;
    const int t = threadIdx.x;
    const float* x = X + (size_t)row * EMB;

    float4 v = *(const float4*)&x[t * 4];
    ssum[t] = v.x + v.y + v.z + v.w;
    ssq[t] = v.x * v.x + v.y * v.y + v.z * v.z + v.w * v.w;
    __syncthreads();
#pragma unroll
    for (int off = 128; off > 0; off >>= 1) {
        if (t < off) {
            ssum[t] += ssum[t + off];
            ssq[t] += ssq[t + off];
        }
        __syncthreads();
    }
    const float mu = ssum[0] * (1.f / EMB);
    const float var = ssq[0] * (1.f / EMB) - mu * mu;
    const float rs = rsqrtf(var + 1e-5f);

    float4 gm = *(const float4*)&gamma[t * 4];
    float4 be = *(const float4*)&beta[t * 4];
    float4 o;
    o.x = (v.x - mu) * rs * gm.x + be.x;
    o.y = (v.y - mu) * rs * gm.y + be.y;
    o.z = (v.z - mu) * rs * gm.z + be.z;
    o.w = (v.w - mu) * rs * gm.w + be.w;
    *(float4*)&out[(size_t)row * EMB + t * 4] = o;
}

// ---------------- launch ----------------
extern "C" void kernel_launch(void* const* d_in, const int* in_sizes, int n_in,
                              void* d_out, int out_size)
{
    const float* query = (const float*)d_in[0];
    const float* key   = (const float*)d_in[1];
    const float* value = (const float*)d_in[2];
    const float* Wq    = (const float*)d_in[3];
    const float* bq    = (const float*)d_in[4];
    const float* Wk    = (const float*)d_in[5];
    const float* bk    = (const float*)d_in[6];
    const float* Wv    = (const float*)d_in[7];
    const float* bv    = (const float*)d_in[8];
    const float* Wo    = (const float*)d_in[9];
    const float* bo    = (const float*)d_in[10];
    const float* ln_g  = (const float*)d_in[11];
    const float* ln_b  = (const float*)d_in[12];
    float* out = (float*)d_out;

    float *Qf, *Kf, *Vf, *TMPp;
    cudaGetSymbolAddress((void**)&Qf, g_Q);
    cudaGetSymbolAddress((void**)&Kf, g_K);
    cudaGetSymbolAddress((void**)&Vf, g_V);
    cudaGetSymbolAddress((void**)&TMPp, g_TMP);
    __nv_bfloat16 *Qph = (__nv_bfloat16*)Qf, *Qpl = Qph + NELEM;
    __nv_bfloat16 *Kph = (__nv_bfloat16*)Kf, *Kpl = Kph + NELEM;
    __nv_bfloat16 *Vph = (__nv_bfloat16*)Vf, *Vpl = Vph + NELEM;

    __nv_bfloat16 *qh, *ql, *kh, *kl, *vh, *vl, *oh, *ol;
    __nv_bfloat16 *wqh, *wql, *wkh, *wkl, *wvh, *wvl, *woh, *wol;
    cudaGetSymbolAddress((void**)&qh, g_qh);  cudaGetSymbolAddress((void**)&ql, g_ql);
    cudaGetSymbolAddress((void**)&kh, g_kh);  cudaGetSymbolAddress((void**)&kl, g_kl);
    cudaGetSymbolAddress((void**)&vh, g_vh);  cudaGetSymbolAddress((void**)&vl, g_vl);
    cudaGetSymbolAddress((void**)&oh, g_oh);  cudaGetSymbolAddress((void**)&ol, g_ol);
    cudaGetSymbolAddress((void**)&wqh, g_wqh); cudaGetSymbolAddress((void**)&wql, g_wql);
    cudaGetSymbolAddress((void**)&wkh, g_wkh); cudaGetSymbolAddress((void**)&wkl, g_wkl);
    cudaGetSymbolAddress((void**)&wvh, g_wvh); cudaGetSymbolAddress((void**)&wvl, g_wvl);
    cudaGetSymbolAddress((void**)&woh, g_woh); cudaGetSymbolAddress((void**)&wol, g_wol);

    static bool attr_set = false;
    if (!attr_set) {
        cudaFuncSetAttribute(gemm_qkv, cudaFuncAttributeMaxDynamicSharedMemorySize, GEMM_SMEM);
        cudaFuncSetAttribute(gemm_out, cudaFuncAttributeMaxDynamicSharedMemorySize, GEMM_SMEM);
        cudaFuncSetAttribute(attn_mma, cudaFuncAttributeMaxDynamicSharedMemorySize, ATTN_SMEM);
        attr_set = true;
    }

    // 1. batched input split
    Split3Args sa;
    sa.x[0] = query; sa.x[1] = key; sa.x[2] = value;
    sa.hi[0] = qh; sa.hi[1] = kh; sa.hi[2] = vh;
    sa.lo[0] = ql; sa.lo[1] = kl; sa.lo[2] = vl;
    fsplit3<<<dim3((unsigned)(NELEM / (256 * 4)), 3), 256>>>(sa);

    // 2. batched weight transpose + split
    WSplit4Args wa;
    wa.W[0] = Wq; wa.W[1] = Wk; wa.W[2] = Wv; wa.W[3] = Wo;
    wa.th[0] = wqh; wa.th[1] = wkh; wa.th[2] = wvh; wa.th[3] = woh;
    wa.tl[0] = wql; wa.tl[1] = wkl; wa.tl[2] = wvl; wa.tl[3] = wol;
    wsplit4<<<dim3(EMB / 32, EMB / 32, 4), dim3(32, 8)>>>(wa);

    // 3. merged Q/K/V projections (Q pre-scaled by 0.125 inside)
    GemmQKVArgs ga;
    ga.Ah[0] = qh; ga.Ah[1] = kh; ga.Ah[2] = vh;
    ga.Al[0] = ql; ga.Al[1] = kl; ga.Al[2] = vl;
    ga.Bh[0] = wqh; ga.Bh[1] = wkh; ga.Bh[2] = wvh;
    ga.Bl[0] = wql; ga.Bl[1] = wkl; ga.Bl[2] = wvl;
    ga.bias[0] = bq; ga.bias[1] = bk; ga.bias[2] = bv;
    ga.Ch[0] = Qph; ga.Ch[1] = Kph; ga.Ch[2] = Vph;
    ga.Cl[0] = Qpl; ga.Cl[1] = Kpl; ga.Cl[2] = Vpl;
    gemm_qkv<<<dim3(EMB / 128, MROWS / 128, 3), 256, GEMM_SMEM>>>(ga);

    // 4. attention
    dim3 attn_grid(SEQ / 128, NH, BATCH);   // (16, 16, 2)
    attn_mma<<<attn_grid, 256, ATTN_SMEM>>>(Qph, Qpl, Kph, Kpl, Vph, Vpl, oh, ol);

    // 5. output projection + residual (fp32 out)
    gemm_out<<<dim3(EMB / 128, MROWS / 128), 256, GEMM_SMEM>>>(oh, ol, woh, wol, bo, query, TMPp);

    // 6. layernorm
    layernorm_kernel<<<MROWS, 256>>>(TMPp, ln_g, ln_b, out);
}